// round 5
// baseline (speedup 1.0000x reference)
#include <cuda_runtime.h>

typedef unsigned long long ull;

#define B_SZ   2048
#define N_INST 8
#define N_FEAT 100
#define N_HID  40
#define NC     40
#define NM     41

#define BT     32
#define NTHR   256

#define GA_C   4800            // floats per c, phase A staged: [f][48] (h in 4 slots of 12, 10 used)
#define GB_C   4480            // floats per c, phase B staged: [h][112] (f in 4 slots of 28, 26 used)
#define BUFSZ  4800            // ring slot size (max of the two)

// Precomputed G in both staged layouts (L2-resident, ~12 MB total)
__device__ float g_GA[N_INST * NC * GA_C];
__device__ float g_GB[N_INST * NC * GB_C];

// ---- packed fp32x2 (Blackwell FFMA2, PTX-only) ----
__device__ __forceinline__ ull ffma2(ull a, ull b, ull c) {
    ull d; asm("fma.rn.f32x2 %0, %1, %2, %3;" : "=l"(d) : "l"(a), "l"(b), "l"(c)); return d;
}
__device__ __forceinline__ ull fmul2(ull a, ull b) {
    ull d; asm("mul.rn.f32x2 %0, %1, %2;" : "=l"(d) : "l"(a), "l"(b)); return d;
}
__device__ __forceinline__ ull pack2(float a, float b) {
    ull d; asm("mov.b64 %0, {%1, %2};" : "=l"(d) : "f"(a), "f"(b)); return d;
}
__device__ __forceinline__ float2 unpk(ull v) {
    float2 r; asm("mov.b64 {%0, %1}, %2;" : "=f"(r.x), "=f"(r.y) : "l"(v)); return r;
}

// ---- cp.async ----
__device__ __forceinline__ void cp16(void* smem_dst, const void* gmem_src) {
    unsigned s = (unsigned)__cvta_generic_to_shared(smem_dst);
    asm volatile("cp.async.cg.shared.global [%0], [%1], 16;" :: "r"(s), "l"(gmem_src) : "memory");
}
__device__ __forceinline__ void cp_commit() { asm volatile("cp.async.commit_group;" ::: "memory"); }
__device__ __forceinline__ void cp_waitn(int n) {
    if (n <= 0)      asm volatile("cp.async.wait_group 0;" ::: "memory");
    else if (n == 1) asm volatile("cp.async.wait_group 1;" ::: "memory");
    else             asm volatile("cp.async.wait_group 2;" ::: "memory");
}
__device__ __forceinline__ void stage(float* dst, const float* src, int n16, int t) {
    for (int idx = t; idx < n16; idx += NTHR)
        cp16((char*)dst + idx * 16, (const char*)src + idx * 16);
}

// ---------------------------------------------------------------------------
// Kernel 1: G = A @ Bp per (i,c), written into both staged layouts.
// ---------------------------------------------------------------------------
__global__ void compute_G_kernel(const float* __restrict__ A,
                                 const float* __restrict__ Bp) {
    __shared__ float As[N_FEAT * NM];
    __shared__ float Bs[NM * N_HID];
    const int ic = blockIdx.x;
    const float* Ap  = A  + (size_t)ic * N_FEAT * NM;
    const float* Bpp = Bp + (size_t)ic * NM * N_HID;
    float* GAo = g_GA + (size_t)ic * GA_C;
    float* GBo = g_GB + (size_t)ic * GB_C;

    for (int idx = threadIdx.x; idx < N_FEAT * NM; idx += blockDim.x) As[idx] = Ap[idx];
    for (int idx = threadIdx.x; idx < NM * N_HID; idx += blockDim.x) Bs[idx] = Bpp[idx];
    // zero pad slots
    for (int idx = threadIdx.x; idx < N_FEAT * 8; idx += blockDim.x) {
        const int f = idx >> 3, k = idx & 7;           // lh = k/2, slot 10/11
        GAo[f * 48 + (k >> 1) * 12 + 10 + (k & 1)] = 0.f;
    }
    for (int idx = threadIdx.x; idx < N_HID * 12; idx += blockDim.x) {
        const int h = idx / 12, k = idx % 12;
        int col = (k < 6) ? ((k >> 1) * 28 + 26 + (k & 1)) : (106 + (k - 6));
        GBo[h * 112 + col] = 0.f;
    }
    __syncthreads();
    for (int idx = threadIdx.x; idx < N_FEAT * N_HID; idx += blockDim.x) {
        const int f = idx / N_HID, h = idx % N_HID;
        float s = 0.f;
#pragma unroll
        for (int m = 0; m < NM; m++) s += As[f * NM + m] * Bs[m * N_HID + h];
        GAo[f * 48 + (h / 10) * 12 + (h % 10)] = s;          // A layout
        GBo[h * 112 + (f / 26) * 28 + (f % 26)] = s;          // B layout (f remapped)
    }
}

// ---------------------------------------------------------------------------
// Kernel 2. SMEM (floats):
//   S0    [3][4800] 14400  G ring (A/B); epilogue: P1/P2 stash (2x3328)
//   xs    [100][32]  3200
//   ms    [ 40][32]  1280
//   hPart [4][40][32] 5120
//   hT    [40][32]   1280
// total 25280 floats = 101120 B -> 2 CTAs/SM
// ---------------------------------------------------------------------------
__global__ __launch_bounds__(NTHR, 2)
void tmsspd_main_kernel(const float* __restrict__ x,
                        const float* __restrict__ mask,
                        const float* __restrict__ bfin,
                        float* __restrict__ out) {
    extern __shared__ float sm[];
    float* S0    = sm;            // 14400
    float* xs    = sm + 14400;    // 3200
    float* ms    = sm + 17600;    // 1280
    float* hPart = sm + 18880;    // 5120
    float* hT    = sm + 24000;    // 1280

    const int i    = blockIdx.y;
    const int b0   = blockIdx.x * BT;
    const int t    = threadIdx.x;
    const int w    = t >> 5;
    const int lane = t & 31;
    const int lb   = lane & 7;    // 8 b-groups (2 b each within the warp's 16-b half)
    const int lh   = lane >> 3;   // 4 slot-groups

    const float* GAsrc = g_GA + (size_t)i * NC * GA_C;
    const float* GBsrc = g_GB + (size_t)i * NC * GB_C;

    // prologue: stage c=0,1 for phase A
    stage(S0,          GAsrc,        GA_C / 4, t); cp_commit();
    stage(S0 + BUFSZ,  GAsrc + GA_C, GA_C / 4, t); cp_commit();

    // load x, mask tiles (transposed [f][b], [c][b])
    for (int idx = t; idx < BT * N_FEAT; idx += NTHR) {
        const int bl = idx / N_FEAT, f = idx % N_FEAT;
        xs[f * BT + bl] = x[((size_t)(b0 + bl) * N_INST + i) * N_FEAT + f];
    }
    for (int idx = t; idx < BT * NC; idx += NTHR) {
        const int bl = idx / NC, c = idx % NC;
        ms[c * BT + bl] = mask[((size_t)(b0 + bl) * N_INST + i) * NC + c];
    }

    // ======================= Phase A =======================
    // warp: bq = w&1 (16-b half), fq = w>>1 (25-f slice)
    // thread: b = bq*16 + lb*2 + {0,1};  h = lh*10 + 0..9 (5 h-pairs)
    {
        const int bq = w & 1, fq = w >> 1;
        const int bb = bq * 16 + lb * 2;
        const int f0 = fq * 25;

        ull acc[2][5];
#pragma unroll
        for (int b = 0; b < 2; b++)
#pragma unroll
            for (int p = 0; p < 5; p++) acc[b][p] = 0ull;

        for (int c = 0; c < NC; c++) {
            __syncthreads();                       // compute c-1 done everywhere
            if (c + 2 < NC) {                      // stage c+2 into free buffer
                stage(S0 + ((c + 2) % 3) * BUFSZ, GAsrc + (size_t)(c + 2) * GA_C,
                      GA_C / 4, t);
                cp_commit();
            }
            cp_waitn(NC - 1 - c >= 2 ? 2 : NC - 1 - c);
            __syncthreads();                       // buffer c visible to all

            const float* Gc = S0 + (c % 3) * BUFSZ;
            const float2 mv = *reinterpret_cast<const float2*>(&ms[c * BT + bb]);
            const ull mpk = pack2(mv.x, mv.y);

#pragma unroll 5
            for (int ff = 0; ff < 25; ff++) {
                const int f = f0 + ff;
                const float2 xv = *reinterpret_cast<const float2*>(&xs[f * BT + bb]);
                const ull xm = fmul2(pack2(xv.x, xv.y), mpk);
                const float2 xf = unpk(xm);
                const ull xd0 = pack2(xf.x, xf.x);
                const ull xd1 = pack2(xf.y, xf.y);

                const float* gp = Gc + f * 48 + lh * 12;
                const ulonglong2 gA = *reinterpret_cast<const ulonglong2*>(gp);
                const ulonglong2 gB = *reinterpret_cast<const ulonglong2*>(gp + 4);
                const ull        gC = *reinterpret_cast<const ull*>(gp + 8);

                acc[0][0] = ffma2(xd0, gA.x, acc[0][0]);
                acc[0][1] = ffma2(xd0, gA.y, acc[0][1]);
                acc[0][2] = ffma2(xd0, gB.x, acc[0][2]);
                acc[0][3] = ffma2(xd0, gB.y, acc[0][3]);
                acc[0][4] = ffma2(xd0, gC,   acc[0][4]);
                acc[1][0] = ffma2(xd1, gA.x, acc[1][0]);
                acc[1][1] = ffma2(xd1, gA.y, acc[1][1]);
                acc[1][2] = ffma2(xd1, gB.x, acc[1][2]);
                acc[1][3] = ffma2(xd1, gB.y, acc[1][3]);
                acc[1][4] = ffma2(xd1, gC,   acc[1][4]);
            }
        }

        // partials: hPart[fq][h][b]
#pragma unroll
        for (int b = 0; b < 2; b++)
#pragma unroll
            for (int p = 0; p < 5; p++) {
                const float2 v = unpk(acc[b][p]);
                const int h = lh * 10 + 2 * p;
                hPart[fq * 1280 + h * BT + bb + b]       = v.x;
                hPart[fq * 1280 + (h + 1) * BT + bb + b] = v.y;
            }
    }
    __syncthreads();

    // stage first two phase-B buffers (S0 free now), then merge hT
    stage(S0,         GBsrc,        GB_C / 4, t); cp_commit();
    stage(S0 + BUFSZ, GBsrc + GB_C, GB_C / 4, t); cp_commit();

    for (int idx = t; idx < N_HID * BT; idx += NTHR)
        hT[idx] = hPart[idx] + hPart[1280 + idx] + hPart[2560 + idx] + hPart[3840 + idx];

    // ======================= Phase B =======================
    // warp: bq = w&1 (16-b half), hq = w>>1 (10-h slice)
    // thread: b = bq*16 + lb*2 + {0,1}; f-slot = lh*28 (26 used -> real f = lh*26 + j)
    const int bq = w & 1, hq = w >> 1;
    const int bb = bq * 16 + lb * 2;
    const int h0 = hq * 10;

    ull acc[2][13];
#pragma unroll
    for (int b = 0; b < 2; b++)
#pragma unroll
        for (int p = 0; p < 13; p++) acc[b][p] = 0ull;

    for (int c = 0; c < NC; c++) {
        __syncthreads();
        if (c + 2 < NC) {
            stage(S0 + ((c + 2) % 3) * BUFSZ, GBsrc + (size_t)(c + 2) * GB_C,
                  GB_C / 4, t);
            cp_commit();
        }
        cp_waitn(NC - 1 - c >= 2 ? 2 : NC - 1 - c);
        __syncthreads();

        const float* Gc = S0 + (c % 3) * BUFSZ;
        const float2 mv = *reinterpret_cast<const float2*>(&ms[c * BT + bb]);
        const ull mpk = pack2(mv.x, mv.y);

#pragma unroll 2
        for (int hh = 0; hh < 10; hh++) {
            const int h = h0 + hh;
            const float2 hv = *reinterpret_cast<const float2*>(&hT[h * BT + bb]);
            const ull hm = fmul2(pack2(hv.x, hv.y), mpk);
            const float2 hf = unpk(hm);
            const ull hd0 = pack2(hf.x, hf.x);
            const ull hd1 = pack2(hf.y, hf.y);

            const float* gp = Gc + h * 112 + lh * 28;
            const ulonglong2 g0 = *reinterpret_cast<const ulonglong2*>(gp);
            const ulonglong2 g1 = *reinterpret_cast<const ulonglong2*>(gp + 4);
            const ulonglong2 g2 = *reinterpret_cast<const ulonglong2*>(gp + 8);
            const ulonglong2 g3 = *reinterpret_cast<const ulonglong2*>(gp + 12);
            const ulonglong2 g4 = *reinterpret_cast<const ulonglong2*>(gp + 16);
            const ulonglong2 g5 = *reinterpret_cast<const ulonglong2*>(gp + 20);
            const ull        g6 = *reinterpret_cast<const ull*>(gp + 24);

            acc[0][0]  = ffma2(hd0, g0.x, acc[0][0]);
            acc[0][1]  = ffma2(hd0, g0.y, acc[0][1]);
            acc[0][2]  = ffma2(hd0, g1.x, acc[0][2]);
            acc[0][3]  = ffma2(hd0, g1.y, acc[0][3]);
            acc[0][4]  = ffma2(hd0, g2.x, acc[0][4]);
            acc[0][5]  = ffma2(hd0, g2.y, acc[0][5]);
            acc[0][6]  = ffma2(hd0, g3.x, acc[0][6]);
            acc[0][7]  = ffma2(hd0, g3.y, acc[0][7]);
            acc[0][8]  = ffma2(hd0, g4.x, acc[0][8]);
            acc[0][9]  = ffma2(hd0, g4.y, acc[0][9]);
            acc[0][10] = ffma2(hd0, g5.x, acc[0][10]);
            acc[0][11] = ffma2(hd0, g5.y, acc[0][11]);
            acc[0][12] = ffma2(hd0, g6,   acc[0][12]);
            acc[1][0]  = ffma2(hd1, g0.x, acc[1][0]);
            acc[1][1]  = ffma2(hd1, g0.y, acc[1][1]);
            acc[1][2]  = ffma2(hd1, g1.x, acc[1][2]);
            acc[1][3]  = ffma2(hd1, g1.y, acc[1][3]);
            acc[1][4]  = ffma2(hd1, g2.x, acc[1][4]);
            acc[1][5]  = ffma2(hd1, g2.y, acc[1][5]);
            acc[1][6]  = ffma2(hd1, g3.x, acc[1][6]);
            acc[1][7]  = ffma2(hd1, g3.y, acc[1][7]);
            acc[1][8]  = ffma2(hd1, g4.x, acc[1][8]);
            acc[1][9]  = ffma2(hd1, g4.y, acc[1][9]);
            acc[1][10] = ffma2(hd1, g5.x, acc[1][10]);
            acc[1][11] = ffma2(hd1, g5.y, acc[1][11]);
            acc[1][12] = ffma2(hd1, g6,   acc[1][12]);
        }
    }

    // ---- cross-hq reduce (4 partials) + epilogue. S0 dead -> P1, P2 stash ----
    float* P1 = S0;           // [32][104]
    float* P2 = S0 + 3328;    // [32][104]
    const int fb = lh * 26;   // real f base for this lane

    __syncthreads();
    if (hq == 1 || hq == 3) {
        float* P = (hq == 1) ? P1 : P2;
#pragma unroll
        for (int b = 0; b < 2; b++)
#pragma unroll
            for (int p = 0; p < 13; p++) {
                const float2 v = unpk(acc[b][p]);
                *reinterpret_cast<float2*>(&P[(bb + b) * 104 + fb + 2 * p]) = v;
            }
    }
    __syncthreads();
    if (hq == 0) {
#pragma unroll
        for (int b = 0; b < 2; b++)
#pragma unroll
            for (int p = 0; p < 13; p++) {
                const float2 s = *reinterpret_cast<const float2*>(&P1[(bb + b) * 104 + fb + 2 * p]);
                acc[b][p] = ffma2(pack2(1.f, 1.f), acc[b][p], pack2(s.x, s.y));
            }
    } else if (hq == 2) {
#pragma unroll
        for (int b = 0; b < 2; b++)
#pragma unroll
            for (int p = 0; p < 13; p++) {
                const float2 s = *reinterpret_cast<const float2*>(&P2[(bb + b) * 104 + fb + 2 * p]);
                const float2 v = unpk(acc[b][p]);
                float2 r; r.x = v.x + s.x; r.y = v.y + s.y;
                *reinterpret_cast<float2*>(&P2[(bb + b) * 104 + fb + 2 * p]) = r;
            }
    }
    __syncthreads();
    if (hq == 0) {
#pragma unroll
        for (int b = 0; b < 2; b++) {
            const size_t orow = ((size_t)(b0 + bb + b) * N_INST + i) * N_FEAT;
#pragma unroll
            for (int p = 0; p < 13; p++) {
                const int f = fb + 2 * p;
                if (f >= N_FEAT) break;          // skip pad pairs (lh==3, p>=11)
                const float2 s  = *reinterpret_cast<const float2*>(&P2[(bb + b) * 104 + f]);
                const float2 bf = *reinterpret_cast<const float2*>(&bfin[i * N_FEAT + f]);
                const float2 v  = unpk(acc[b][p]);
                float2 r;
                r.x = fmaxf(v.x + s.x + bf.x, 0.f);
                r.y = fmaxf(v.y + s.y + bf.y, 0.f);
                *reinterpret_cast<float2*>(&out[orow + f]) = r;
            }
        }
    }
}

// ---------------------------------------------------------------------------
extern "C" void kernel_launch(void* const* d_in, const int* in_sizes, int n_in,
                              void* d_out, int out_size) {
    (void)in_sizes; (void)n_in; (void)out_size;
    const float* x    = (const float*)d_in[0];
    const float* mask = (const float*)d_in[1];
    const float* A    = (const float*)d_in[2];
    const float* Bp   = (const float*)d_in[3];
    const float* bfin = (const float*)d_in[4];
    float* out = (float*)d_out;

    const int smem_bytes = 25280 * 4;   // 101120
    cudaFuncSetAttribute(tmsspd_main_kernel,
                         cudaFuncAttributeMaxDynamicSharedMemorySize, smem_bytes);

    compute_G_kernel<<<N_INST * NC, 128>>>(A, Bp);

    dim3 grid(B_SZ / BT, N_INST);
    tmsspd_main_kernel<<<grid, NTHR, smem_bytes>>>(x, mask, bfin, out);
}

// round 7
// speedup vs baseline: 2.3917x; 2.3917x over previous
#include <cuda_runtime.h>
#include <cuda_bf16.h>
#include <cstdint>

#define B_SZ   2048
#define N_INST 8
#define N_FEAT 100
#define N_HID  40
#define NC     40
#define NM     41
#define NTHR   256

// fragment-image sizes (bytes) per (i,c)
#define FRA_SPLIT 8960            // phase A B-op: 7 kstep x 5 ntile x 32 thr x 8B
#define IMGA_C    17920           // hi || lo
#define FRB_SPLIT 9984            // phase B B-op: 3 kstep x 13 ntile x 32 thr x 8B
#define IMGB_C    19968
#define RING_STRIDE 19968

// smem byte layout
#define SM_RING 0                 // 2 x 19968 = 39936
#define SM_MSK  39936             // mask [40][128] f32 = 20480
#define SM_HX   60416             // h exchange [128][40] f32 = 20480
#define SM_BIAS 80896             // 512
#define SM_TOTAL 81408

__device__ __align__(16) unsigned char g_imgA[N_INST * NC * IMGA_C];  // 5.73 MB
__device__ __align__(16) unsigned char g_imgB[N_INST * NC * IMGB_C];  // 6.39 MB

// ===================== helpers =====================
__device__ __forceinline__ uint32_t smem_u32(const void* p) {
    return (uint32_t)__cvta_generic_to_shared(p);
}
__device__ __forceinline__ void cp16(uint32_t smem_dst, const void* gmem_src) {
    asm volatile("cp.async.cg.shared.global [%0], [%1], 16;" :: "r"(smem_dst), "l"(gmem_src) : "memory");
}
#define CP_COMMIT() asm volatile("cp.async.commit_group;" ::: "memory")
__device__ __forceinline__ void cp_waitn(int n) {
    if (n == 0) asm volatile("cp.async.wait_group 0;" ::: "memory");
    else        asm volatile("cp.async.wait_group 1;" ::: "memory");
}
__device__ __forceinline__ void stageN(uint32_t dst, const unsigned char* src, int bytes, int tid) {
    for (int o = tid * 16; o < bytes; o += NTHR * 16) cp16(dst + o, src + o);
}
// bf16 MMA m16n8k16, fp32 accum (sm_80 baseline -> legal on compute_103)
__device__ __forceinline__ void mma_bf16(float* d, const uint32_t* a, uint2 b) {
    asm volatile("mma.sync.aligned.m16n8k16.row.col.f32.bf16.bf16.f32 "
                 "{%0,%1,%2,%3},{%4,%5,%6,%7},{%8,%9},{%0,%1,%2,%3};"
                 : "+f"(d[0]), "+f"(d[1]), "+f"(d[2]), "+f"(d[3])
                 : "r"(a[0]), "r"(a[1]), "r"(a[2]), "r"(a[3]), "r"(b.x), "r"(b.y));
}
__device__ __forceinline__ uint32_t pack_bf2(float a, float b) {
    __nv_bfloat162 t = __floats2bfloat162_rn(a, b);   // x -> low half
    return *reinterpret_cast<uint32_t*>(&t);
}
__device__ __forceinline__ void split_pair(float a, float b, uint32_t& hi, uint32_t& lo) {
    const __nv_bfloat16 ah = __float2bfloat16(a), bh = __float2bfloat16(b);
    hi = pack_bf2(a, b);
    lo = pack_bf2(a - __bfloat162float(ah), b - __bfloat162float(bh));
}

// ===================== Kernel 1: G -> fragment images =====================
__global__ void compute_G_kernel(const float* __restrict__ A, const float* __restrict__ Bp) {
    __shared__ float As[N_FEAT * NM];
    __shared__ float Bs[NM * N_HID];
    const int ic = blockIdx.x;
    const float* Ap  = A  + (size_t)ic * N_FEAT * NM;
    const float* Bpp = Bp + (size_t)ic * NM * N_HID;
    unsigned char* iA = g_imgA + (size_t)ic * IMGA_C;
    unsigned char* iB = g_imgB + (size_t)ic * IMGB_C;

    for (int idx = threadIdx.x; idx < N_FEAT * NM; idx += blockDim.x) As[idx] = Ap[idx];
    for (int idx = threadIdx.x; idx < NM * N_HID; idx += blockDim.x) Bs[idx] = Bpp[idx];
    for (int idx = threadIdx.x; idx < IMGA_C / 16; idx += blockDim.x)
        reinterpret_cast<uint4*>(iA)[idx] = make_uint4(0, 0, 0, 0);
    for (int idx = threadIdx.x; idx < IMGB_C / 16; idx += blockDim.x)
        reinterpret_cast<uint4*>(iB)[idx] = make_uint4(0, 0, 0, 0);
    __syncthreads();

    for (int idx = threadIdx.x; idx < N_FEAT * N_HID; idx += blockDim.x) {
        const int f = idx / N_HID, h = idx % N_HID;
        float s = 0.f;
#pragma unroll
        for (int m = 0; m < NM; m++) s += As[f * NM + m] * Bs[m * N_HID + h];
        const __nv_bfloat16 shb = __float2bfloat16(s);
        const __nv_bfloat16 slb = __float2bfloat16(s - __bfloat162float(shb));

        // phase A image: B operand [k=f (112 pad)][n=h], tile (kst,nt), thread T=(h%8)*4+q
        {
            const int kst = f >> 4, fr = f & 15;
            const int half = fr >> 3, q = (fr >> 1) & 3, lo = f & 1;
            const int T = ((h & 7) << 2) | q;
            const int off = (((kst * 5 + (h >> 3)) * 32 + T) << 3) + (half << 2) + (lo << 1);
            *reinterpret_cast<__nv_bfloat16*>(iA + off)             = shb;
            *reinterpret_cast<__nv_bfloat16*>(iA + FRA_SPLIT + off) = slb;
        }
        // phase B image: B operand [k=h (48 pad)][n=f (104 pad)]
        {
            const int kst = h >> 4, hr = h & 15;
            const int half = hr >> 3, q = (hr >> 1) & 3, lo = h & 1;
            const int T = ((f & 7) << 2) | q;
            const int off = (((kst * 13 + (f >> 3)) * 32 + T) << 3) + (half << 2) + (lo << 1);
            *reinterpret_cast<__nv_bfloat16*>(iB + off)             = shb;
            *reinterpret_cast<__nv_bfloat16*>(iB + FRB_SPLIT + off) = slb;
        }
    }
}

// ===================== Kernel 2: fused main =====================
__global__ __launch_bounds__(NTHR)
void tmsspd_main_kernel(const float* __restrict__ x, const float* __restrict__ mask,
                        const float* __restrict__ bfin, float* __restrict__ out) {
    extern __shared__ char smem[];
    const uint32_t sb_ring = smem_u32(smem) + SM_RING;
    float* mskS  = reinterpret_cast<float*>(smem + SM_MSK);
    float* hX    = reinterpret_cast<float*>(smem + SM_HX);
    float* biasS = reinterpret_cast<float*>(smem + SM_BIAS);

    const int i   = blockIdx.y;
    const int b0  = blockIdx.x * 128;
    const int tid = threadIdx.x;
    const int w   = tid >> 5;
    const int T   = tid & 31;
    const int q   = T & 3;        // k-quad
    const int tr  = T >> 2;       // row-in-tile
    const int r0  = w * 16 + tr;  // warp owns rows [w*16, w*16+16)
    const int r1  = r0 + 8;

    const unsigned char* imgA = g_imgA + (size_t)(i * NC) * IMGA_C;
    const unsigned char* imgB = g_imgB + (size_t)(i * NC) * IMGB_C;

    // stage A-image c=0 ASAP
    stageN(sb_ring, imgA, IMGA_C, tid); CP_COMMIT();

    // mask + bias tiles
    for (int idx = tid; idx < 128 * NC; idx += NTHR) {
        const int r = idx / NC, c = idx % NC;
        mskS[c * 128 + r] = mask[((size_t)(b0 + r) * N_INST + i) * NC + c];
    }
    if (tid < N_FEAT) biasS[tid] = bfin[i * N_FEAT + tid];

    // X fragments straight from gmem (rows r0/r1, bf16 split), K padded to 112
    uint32_t xhi[7][4], xlo[7][4];
    {
        const float* xr0 = x + ((size_t)(b0 + r0) * N_INST + i) * N_FEAT;
        const float* xr1 = x + ((size_t)(b0 + r1) * N_INST + i) * N_FEAT;
#pragma unroll
        for (int kst = 0; kst < 7; kst++) {
#pragma unroll
            for (int half = 0; half < 2; half++) {
                const int kk = kst * 16 + q * 2 + half * 8;
                float2 v0 = make_float2(0.f, 0.f), v1 = make_float2(0.f, 0.f);
                if (kk < N_FEAT) {
                    v0 = *reinterpret_cast<const float2*>(xr0 + kk);
                    v1 = *reinterpret_cast<const float2*>(xr1 + kk);
                }
                split_pair(v0.x, v0.y, xhi[kst][half * 2],     xlo[kst][half * 2]);
                split_pair(v1.x, v1.y, xhi[kst][half * 2 + 1], xlo[kst][half * 2 + 1]);
            }
        }
    }

    // ======================= Phase A =======================
    float hacc[5][4];
#pragma unroll
    for (int nt = 0; nt < 5; nt++)
#pragma unroll
        for (int j = 0; j < 4; j++) hacc[nt][j] = 0.f;

    for (int c = 0; c < NC; c++) {
        __syncthreads();                                  // buf (c+1)&1 free
        if (c + 1 < NC) {
            stageN(sb_ring + ((c + 1) & 1) * RING_STRIDE,
                   imgA + (size_t)(c + 1) * IMGA_C, IMGA_C, tid);
            CP_COMMIT();
        }
        cp_waitn(c + 1 < NC ? 1 : 0);
        __syncthreads();                                  // buf c visible to all

        const char* buf = smem + SM_RING + (c & 1) * RING_STRIDE;
        float d[5][4];
#pragma unroll
        for (int nt = 0; nt < 5; nt++)
#pragma unroll
            for (int j = 0; j < 4; j++) d[nt][j] = 0.f;

#pragma unroll
        for (int kst = 0; kst < 7; kst++) {
#pragma unroll
            for (int nt = 0; nt < 5; nt++) {
                const char* bp = buf + (((kst * 5 + nt) * 32 + T) << 3);
                const uint2 bh = *reinterpret_cast<const uint2*>(bp);
                const uint2 bl = *reinterpret_cast<const uint2*>(bp + FRA_SPLIT);
                mma_bf16(d[nt], xhi[kst], bh);
                mma_bf16(d[nt], xhi[kst], bl);
                mma_bf16(d[nt], xlo[kst], bh);
            }
        }
        const float m0 = mskS[c * 128 + r0];
        const float m1 = mskS[c * 128 + r1];
#pragma unroll
        for (int nt = 0; nt < 5; nt++) {
            hacc[nt][0] = fmaf(m0, d[nt][0], hacc[nt][0]);
            hacc[nt][1] = fmaf(m0, d[nt][1], hacc[nt][1]);
            hacc[nt][2] = fmaf(m1, d[nt][2], hacc[nt][2]);
            hacc[nt][3] = fmaf(m1, d[nt][3], hacc[nt][3]);
        }
    }

    // h -> SMEM (warp-local exchange), then build A-fragments for phase B
#pragma unroll
    for (int nt = 0; nt < 5; nt++) {
        const int col = nt * 8 + q * 2;
        hX[r0 * N_HID + col]     = hacc[nt][0];
        hX[r0 * N_HID + col + 1] = hacc[nt][1];
        hX[r1 * N_HID + col]     = hacc[nt][2];
        hX[r1 * N_HID + col + 1] = hacc[nt][3];
    }
    // stage B-image c=0 into buf0 (free: phase A c=39 used buf1)
    stageN(sb_ring, imgB, IMGB_C, tid); CP_COMMIT();
    __syncwarp();

    uint32_t hh[3][4], hl[3][4];
#pragma unroll
    for (int kst = 0; kst < 3; kst++) {
#pragma unroll
        for (int half = 0; half < 2; half++) {
            const int kk = kst * 16 + q * 2 + half * 8;
            float2 v0 = make_float2(0.f, 0.f), v1 = make_float2(0.f, 0.f);
            if (kk < N_HID) {
                v0 = *reinterpret_cast<const float2*>(&hX[r0 * N_HID + kk]);
                v1 = *reinterpret_cast<const float2*>(&hX[r1 * N_HID + kk]);
            }
            split_pair(v0.x, v0.y, hh[kst][half * 2],     hl[kst][half * 2]);
            split_pair(v1.x, v1.y, hh[kst][half * 2 + 1], hl[kst][half * 2 + 1]);
        }
    }

    // ======================= Phase B =======================
    float oacc[13][4];
#pragma unroll
    for (int nt = 0; nt < 13; nt++)
#pragma unroll
        for (int j = 0; j < 4; j++) oacc[nt][j] = 0.f;

    for (int c = 0; c < NC; c++) {
        __syncthreads();
        if (c + 1 < NC) {
            stageN(sb_ring + ((c + 1) & 1) * RING_STRIDE,
                   imgB + (size_t)(c + 1) * IMGB_C, IMGB_C, tid);
            CP_COMMIT();
        }
        cp_waitn(c + 1 < NC ? 1 : 0);
        __syncthreads();

        const char* buf = smem + SM_RING + (c & 1) * RING_STRIDE;
        const uint32_t keep0 = (mskS[c * 128 + r0] != 0.f) ? 0xFFFFFFFFu : 0u;
        const uint32_t keep1 = (mskS[c * 128 + r1] != 0.f) ? 0xFFFFFFFFu : 0u;

#pragma unroll
        for (int kst = 0; kst < 3; kst++) {
            uint32_t ah[4], al[4];
            ah[0] = hh[kst][0] & keep0; ah[1] = hh[kst][1] & keep1;
            ah[2] = hh[kst][2] & keep0; ah[3] = hh[kst][3] & keep1;
            al[0] = hl[kst][0] & keep0; al[1] = hl[kst][1] & keep1;
            al[2] = hl[kst][2] & keep0; al[3] = hl[kst][3] & keep1;
#pragma unroll
            for (int nt = 0; nt < 13; nt++) {
                const char* bp = buf + (((kst * 13 + nt) * 32 + T) << 3);
                const uint2 bh = *reinterpret_cast<const uint2*>(bp);
                const uint2 bl = *reinterpret_cast<const uint2*>(bp + FRB_SPLIT);
                mma_bf16(oacc[nt], ah, bh);
                mma_bf16(oacc[nt], ah, bl);
                mma_bf16(oacc[nt], al, bh);
            }
        }
    }

    // ======================= epilogue =======================
    float* o0 = out + ((size_t)(b0 + r0) * N_INST + i) * N_FEAT;
    float* o1 = out + ((size_t)(b0 + r1) * N_INST + i) * N_FEAT;
#pragma unroll
    for (int nt = 0; nt < 13; nt++) {
        const int col = nt * 8 + q * 2;
        if (col < N_FEAT) {
            const float2 bf = *reinterpret_cast<const float2*>(&biasS[col]);
            float2 a, b;
            a.x = fmaxf(oacc[nt][0] + bf.x, 0.f);
            a.y = fmaxf(oacc[nt][1] + bf.y, 0.f);
            b.x = fmaxf(oacc[nt][2] + bf.x, 0.f);
            b.y = fmaxf(oacc[nt][3] + bf.y, 0.f);
            *reinterpret_cast<float2*>(o0 + col) = a;
            *reinterpret_cast<float2*>(o1 + col) = b;
        }
    }
}

// ---------------------------------------------------------------------------
extern "C" void kernel_launch(void* const* d_in, const int* in_sizes, int n_in,
                              void* d_out, int out_size) {
    (void)in_sizes; (void)n_in; (void)out_size;
    const float* x    = (const float*)d_in[0];
    const float* mask = (const float*)d_in[1];
    const float* A    = (const float*)d_in[2];
    const float* Bp   = (const float*)d_in[3];
    const float* bfin = (const float*)d_in[4];
    float* out = (float*)d_out;

    cudaFuncSetAttribute(tmsspd_main_kernel,
                         cudaFuncAttributeMaxDynamicSharedMemorySize, SM_TOTAL);

    compute_G_kernel<<<N_INST * NC, 128>>>(A, Bp);

    dim3 grid(B_SZ / 128, N_INST);
    tmsspd_main_kernel<<<grid, NTHR, SM_TOTAL>>>(x, mask, bfin, out);
}

// round 8
// speedup vs baseline: 2.5784x; 1.0781x over previous
#include <cuda_runtime.h>
#include <cuda_bf16.h>
#include <cstdint>

#define B_SZ   2048
#define N_INST 8
#define N_FEAT 100
#define N_HID  40
#define NC     40
#define NM     41
#define NTHR   256

// fragment-image sizes (bytes) per (i,c); hi/lo interleaved per 16B word
#define IMGA_C 17920              // 7 kstep x 5 ntile x 32 thr x 16B
#define IMGB_C 19968              // 3 kstep x 13 ntile x 32 thr x 16B
#define SLOTA  (2*IMGA_C)         // 35840 : two c's per ring slot
#define SLOTB  (2*IMGB_C)         // 39936
#define RING_STRIDE 39936

// smem byte layout (main kernel)
#define SM_RING 0                 // 2 x 39936 = 79872
#define SM_MSK  79872             // mask [40][128] f32 = 20480
#define SM_HX   100352            // h exchange [128][40] f32 = 20480
#define SM_BIAS 120832            // 512
#define SM_TOTAL 121344

__device__ __align__(16) unsigned char g_imgA[N_INST * NC * IMGA_C];  // 5.73 MB
__device__ __align__(16) unsigned char g_imgB[N_INST * NC * IMGB_C];  // 6.39 MB

// ===================== helpers =====================
__device__ __forceinline__ uint32_t smem_u32(const void* p) {
    return (uint32_t)__cvta_generic_to_shared(p);
}
__device__ __forceinline__ void cp16(uint32_t smem_dst, const void* gmem_src) {
    asm volatile("cp.async.cg.shared.global [%0], [%1], 16;" :: "r"(smem_dst), "l"(gmem_src) : "memory");
}
#define CP_COMMIT() asm volatile("cp.async.commit_group;" ::: "memory")
__device__ __forceinline__ void cp_waitn(int n) {
    if (n == 0) asm volatile("cp.async.wait_group 0;" ::: "memory");
    else        asm volatile("cp.async.wait_group 1;" ::: "memory");
}
__device__ __forceinline__ void stageN(uint32_t dst, const unsigned char* src, int bytes, int tid) {
    for (int o = tid * 16; o < bytes; o += NTHR * 16) cp16(dst + o, src + o);
}
// bf16 MMA m16n8k16, fp32 accum (sm_80 baseline -> legal on compute_103)
__device__ __forceinline__ void mma_bf16(float* d, const uint32_t* a, uint32_t b0, uint32_t b1) {
    asm volatile("mma.sync.aligned.m16n8k16.row.col.f32.bf16.bf16.f32 "
                 "{%0,%1,%2,%3},{%4,%5,%6,%7},{%8,%9},{%0,%1,%2,%3};"
                 : "+f"(d[0]), "+f"(d[1]), "+f"(d[2]), "+f"(d[3])
                 : "r"(a[0]), "r"(a[1]), "r"(a[2]), "r"(a[3]), "r"(b0), "r"(b1));
}
__device__ __forceinline__ uint32_t pack_bf2(float a, float b) {
    __nv_bfloat162 t = __floats2bfloat162_rn(a, b);   // x -> low half
    return *reinterpret_cast<uint32_t*>(&t);
}
__device__ __forceinline__ void split_pair(float a, float b, uint32_t& hi, uint32_t& lo) {
    const __nv_bfloat16 ah = __float2bfloat16(a), bh = __float2bfloat16(b);
    hi = pack_bf2(a, b);
    lo = pack_bf2(a - __bfloat162float(ah), b - __bfloat162float(bh));
}
// build one interleaved fragment word from 4 fp32 values v[half][lo]
__device__ __forceinline__ uint4 frag_word(float v00, float v01, float v10, float v11) {
    uint4 w;
    uint32_t h0, l0, h1, l1;
    split_pair(v00, v01, h0, l0);
    split_pair(v10, v11, h1, l1);
    w.x = h0; w.y = h1; w.z = l0; w.w = l1;
    return w;
}

// ===================== Kernel 1: G -> fragment images (coalesced) =====================
__global__ void compute_G_kernel(const float* __restrict__ A, const float* __restrict__ Bp) {
    __shared__ float As[N_FEAT * NM];     // 4100
    __shared__ float Bs[NM * N_HID];      // 1640
    __shared__ float sS[N_FEAT * N_HID];  // 4000
    const int ic = blockIdx.x;
    const float* Ap  = A  + (size_t)ic * N_FEAT * NM;
    const float* Bpp = Bp + (size_t)ic * NM * N_HID;
    uint4* iA = reinterpret_cast<uint4*>(g_imgA + (size_t)ic * IMGA_C);
    uint4* iB = reinterpret_cast<uint4*>(g_imgB + (size_t)ic * IMGB_C);

    for (int idx = threadIdx.x; idx < N_FEAT * NM; idx += blockDim.x) As[idx] = Ap[idx];
    for (int idx = threadIdx.x; idx < NM * N_HID; idx += blockDim.x) Bs[idx] = Bpp[idx];
    __syncthreads();

    for (int idx = threadIdx.x; idx < N_FEAT * N_HID; idx += blockDim.x) {
        const int f = idx / N_HID, h = idx % N_HID;
        float s = 0.f;
#pragma unroll
        for (int m = 0; m < NM; m++) s += As[f * NM + m] * Bs[m * N_HID + h];
        sS[idx] = s;
    }
    __syncthreads();

    // phase A image: B operand [k=f][n=h]; word idx = (kst*5+nt)*32+T
    for (int widx = threadIdx.x; widx < 7 * 5 * 32; widx += blockDim.x) {
        const int kst = widx / 160, rem = widx % 160;
        const int nt = rem / 32, T = rem % 32;
        const int q = T & 3, tr = T >> 2;
        const int n = nt * 8 + tr;                 // h index, < 40
        float v[2][2];
#pragma unroll
        for (int half = 0; half < 2; half++)
#pragma unroll
            for (int lo = 0; lo < 2; lo++) {
                const int f = kst * 16 + q * 2 + half * 8 + lo;
                v[half][lo] = (f < N_FEAT) ? sS[f * N_HID + n] : 0.f;
            }
        iA[widx] = frag_word(v[0][0], v[0][1], v[1][0], v[1][1]);
    }
    // phase B image: B operand [k=h][n=f]; word idx = (kst*13+nt)*32+T
    for (int widx = threadIdx.x; widx < 3 * 13 * 32; widx += blockDim.x) {
        const int kst = widx / 416, rem = widx % 416;
        const int nt = rem / 32, T = rem % 32;
        const int q = T & 3, tr = T >> 2;
        const int f = nt * 8 + tr;                 // f index, may be >= 100
        float v[2][2];
#pragma unroll
        for (int half = 0; half < 2; half++)
#pragma unroll
            for (int lo = 0; lo < 2; lo++) {
                const int h = kst * 16 + q * 2 + half * 8 + lo;
                v[half][lo] = (f < N_FEAT && h < N_HID) ? sS[f * N_HID + h] : 0.f;
            }
        iB[widx] = frag_word(v[0][0], v[0][1], v[1][0], v[1][1]);
    }
}

// ===================== Kernel 2: fused main =====================
__global__ __launch_bounds__(NTHR)
void tmsspd_main_kernel(const float* __restrict__ x, const float* __restrict__ mask,
                        const float* __restrict__ bfin, float* __restrict__ out) {
    extern __shared__ char smem[];
    const uint32_t sb_ring = smem_u32(smem) + SM_RING;
    float* mskS  = reinterpret_cast<float*>(smem + SM_MSK);
    float* hX    = reinterpret_cast<float*>(smem + SM_HX);
    float* biasS = reinterpret_cast<float*>(smem + SM_BIAS);

    const int i   = blockIdx.y;
    const int b0  = blockIdx.x * 128;
    const int tid = threadIdx.x;
    const int w   = tid >> 5;
    const int T   = tid & 31;
    const int q   = T & 3;
    const int tr  = T >> 2;
    const int r0  = w * 16 + tr;
    const int r1  = r0 + 8;

    const unsigned char* imgA = g_imgA + (size_t)(i * NC) * IMGA_C;
    const unsigned char* imgB = g_imgB + (size_t)(i * NC) * IMGB_C;

    // prologue: stage A pair0 (c=0,1)
    stageN(sb_ring, imgA, SLOTA, tid); CP_COMMIT();

    for (int idx = tid; idx < 128 * NC; idx += NTHR) {
        const int r = idx / NC, c = idx % NC;
        mskS[c * 128 + r] = mask[((size_t)(b0 + r) * N_INST + i) * NC + c];
    }
    if (tid < N_FEAT) biasS[tid] = bfin[i * N_FEAT + tid];

    // X fragments from gmem (rows r0/r1, bf16 split), K padded to 112
    uint32_t xhi[7][4], xlo[7][4];
    {
        const float* xr0 = x + ((size_t)(b0 + r0) * N_INST + i) * N_FEAT;
        const float* xr1 = x + ((size_t)(b0 + r1) * N_INST + i) * N_FEAT;
#pragma unroll
        for (int kst = 0; kst < 7; kst++) {
#pragma unroll
            for (int half = 0; half < 2; half++) {
                const int kk = kst * 16 + q * 2 + half * 8;
                float2 v0 = make_float2(0.f, 0.f), v1 = make_float2(0.f, 0.f);
                if (kk < N_FEAT) {
                    v0 = *reinterpret_cast<const float2*>(xr0 + kk);
                    v1 = *reinterpret_cast<const float2*>(xr1 + kk);
                }
                split_pair(v0.x, v0.y, xhi[kst][half * 2],     xlo[kst][half * 2]);
                split_pair(v1.x, v1.y, xhi[kst][half * 2 + 1], xlo[kst][half * 2 + 1]);
            }
        }
    }

    // ======================= Phase A (20 pair-iterations) =======================
    float hacc[5][4];
#pragma unroll
    for (int nt = 0; nt < 5; nt++)
#pragma unroll
        for (int j = 0; j < 4; j++) hacc[nt][j] = 0.f;

    for (int cp = 0; cp < 20; cp++) {
        __syncthreads();                                  // other slot free
        if (cp + 1 < 20) {
            stageN(sb_ring + ((cp + 1) & 1) * RING_STRIDE,
                   imgA + (size_t)(cp + 1) * SLOTA, SLOTA, tid);
            CP_COMMIT();
        }
        cp_waitn(cp + 1 < 20 ? 1 : 0);
        __syncthreads();                                  // slot cp&1 visible

        const char* base = smem + SM_RING + (cp & 1) * RING_STRIDE;
#pragma unroll
        for (int cc = 0; cc < 2; cc++) {
            const int c = 2 * cp + cc;
            const char* buf = base + cc * IMGA_C;
            float d[5][4];
#pragma unroll
            for (int nt = 0; nt < 5; nt++)
#pragma unroll
                for (int j = 0; j < 4; j++) d[nt][j] = 0.f;

#pragma unroll
            for (int kst = 0; kst < 7; kst++) {
#pragma unroll
                for (int nt = 0; nt < 5; nt++) {
                    const uint4 wv = *reinterpret_cast<const uint4*>(
                        buf + (((kst * 5 + nt) * 32 + T) << 4));
                    mma_bf16(d[nt], xhi[kst], wv.x, wv.y);
                    mma_bf16(d[nt], xhi[kst], wv.z, wv.w);
                    mma_bf16(d[nt], xlo[kst], wv.x, wv.y);
                }
            }
            const float m0 = mskS[c * 128 + r0];
            const float m1 = mskS[c * 128 + r1];
#pragma unroll
            for (int nt = 0; nt < 5; nt++) {
                hacc[nt][0] = fmaf(m0, d[nt][0], hacc[nt][0]);
                hacc[nt][1] = fmaf(m0, d[nt][1], hacc[nt][1]);
                hacc[nt][2] = fmaf(m1, d[nt][2], hacc[nt][2]);
                hacc[nt][3] = fmaf(m1, d[nt][3], hacc[nt][3]);
            }
        }
    }

    // h exchange (warp-local) + stage B pair0 into slot0 (free: pair18 done, pair19 in slot1)
#pragma unroll
    for (int nt = 0; nt < 5; nt++) {
        const int col = nt * 8 + q * 2;
        hX[r0 * N_HID + col]     = hacc[nt][0];
        hX[r0 * N_HID + col + 1] = hacc[nt][1];
        hX[r1 * N_HID + col]     = hacc[nt][2];
        hX[r1 * N_HID + col + 1] = hacc[nt][3];
    }
    stageN(sb_ring, imgB, SLOTB, tid); CP_COMMIT();
    __syncwarp();

    uint32_t hh[3][4], hl[3][4];
#pragma unroll
    for (int kst = 0; kst < 3; kst++) {
#pragma unroll
        for (int half = 0; half < 2; half++) {
            const int kk = kst * 16 + q * 2 + half * 8;
            float2 v0 = make_float2(0.f, 0.f), v1 = make_float2(0.f, 0.f);
            if (kk < N_HID) {
                v0 = *reinterpret_cast<const float2*>(&hX[r0 * N_HID + kk]);
                v1 = *reinterpret_cast<const float2*>(&hX[r1 * N_HID + kk]);
            }
            split_pair(v0.x, v0.y, hh[kst][half * 2],     hl[kst][half * 2]);
            split_pair(v1.x, v1.y, hh[kst][half * 2 + 1], hl[kst][half * 2 + 1]);
        }
    }

    // ======================= Phase B (20 pair-iterations) =======================
    float oacc[13][4];
#pragma unroll
    for (int nt = 0; nt < 13; nt++)
#pragma unroll
        for (int j = 0; j < 4; j++) oacc[nt][j] = 0.f;

    for (int cp = 0; cp < 20; cp++) {
        __syncthreads();
        if (cp + 1 < 20) {
            stageN(sb_ring + ((cp + 1) & 1) * RING_STRIDE,
                   imgB + (size_t)(cp + 1) * SLOTB, SLOTB, tid);
            CP_COMMIT();
        }
        cp_waitn(cp + 1 < 20 ? 1 : 0);
        __syncthreads();

        const char* base = smem + SM_RING + (cp & 1) * RING_STRIDE;
#pragma unroll
        for (int cc = 0; cc < 2; cc++) {
            const int c = 2 * cp + cc;
            const char* buf = base + cc * IMGB_C;
            const uint32_t keep0 = (mskS[c * 128 + r0] != 0.f) ? 0xFFFFFFFFu : 0u;
            const uint32_t keep1 = (mskS[c * 128 + r1] != 0.f) ? 0xFFFFFFFFu : 0u;

#pragma unroll
            for (int kst = 0; kst < 3; kst++) {
                uint32_t ah[4], al[4];
                ah[0] = hh[kst][0] & keep0; ah[1] = hh[kst][1] & keep1;
                ah[2] = hh[kst][2] & keep0; ah[3] = hh[kst][3] & keep1;
                al[0] = hl[kst][0] & keep0; al[1] = hl[kst][1] & keep1;
                al[2] = hl[kst][2] & keep0; al[3] = hl[kst][3] & keep1;
#pragma unroll
                for (int nt = 0; nt < 13; nt++) {
                    const uint4 wv = *reinterpret_cast<const uint4*>(
                        buf + (((kst * 13 + nt) * 32 + T) << 4));
                    mma_bf16(oacc[nt], ah, wv.x, wv.y);
                    mma_bf16(oacc[nt], ah, wv.z, wv.w);
                    mma_bf16(oacc[nt], al, wv.x, wv.y);
                }
            }
        }
    }

    // ======================= epilogue =======================
    float* o0 = out + ((size_t)(b0 + r0) * N_INST + i) * N_FEAT;
    float* o1 = out + ((size_t)(b0 + r1) * N_INST + i) * N_FEAT;
#pragma unroll
    for (int nt = 0; nt < 13; nt++) {
        const int col = nt * 8 + q * 2;
        if (col < N_FEAT) {
            const float2 bf = *reinterpret_cast<const float2*>(&biasS[col]);
            float2 a, b;
            a.x = fmaxf(oacc[nt][0] + bf.x, 0.f);
            a.y = fmaxf(oacc[nt][1] + bf.y, 0.f);
            b.x = fmaxf(oacc[nt][2] + bf.x, 0.f);
            b.y = fmaxf(oacc[nt][3] + bf.y, 0.f);
            *reinterpret_cast<float2*>(o0 + col) = a;
            *reinterpret_cast<float2*>(o1 + col) = b;
        }
    }
}

// ---------------------------------------------------------------------------
extern "C" void kernel_launch(void* const* d_in, const int* in_sizes, int n_in,
                              void* d_out, int out_size) {
    (void)in_sizes; (void)n_in; (void)out_size;
    const float* x    = (const float*)d_in[0];
    const float* mask = (const float*)d_in[1];
    const float* A    = (const float*)d_in[2];
    const float* Bp   = (const float*)d_in[3];
    const float* bfin = (const float*)d_in[4];
    float* out = (float*)d_out;

    cudaFuncSetAttribute(tmsspd_main_kernel,
                         cudaFuncAttributeMaxDynamicSharedMemorySize, SM_TOTAL);

    compute_G_kernel<<<N_INST * NC, 128>>>(A, Bp);

    dim3 grid(B_SZ / 128, N_INST);
    tmsspd_main_kernel<<<grid, NTHR, SM_TOTAL>>>(x, mask, bfin, out);
}

// round 9
// speedup vs baseline: 2.9469x; 1.1429x over previous
#include <cuda_runtime.h>
#include <cuda_bf16.h>
#include <cstdint>

#define B_SZ   2048
#define N_INST 8
#define N_FEAT 100
#define N_HID  40
#define NC     40
#define NM     41
#define NTHR   256

// fragment-image sizes (bytes) per (i,c); hi/lo interleaved per 16B word
#define IMGA_C 17920              // 7 kstep x 5 ntile x 32 thr x 16B
#define IMGB_C 19968              // 3 kstep x 13 ntile x 32 thr x 16B
#define SLOTA  (2*IMGA_C)         // 35840 : two c's per ring slot
#define SLOTB  (2*IMGB_C)         // 39936
#define RING_STRIDE 39936

// smem byte layout (main kernel): 3-slot ring
#define SM_RING 0                 // 3 x 39936 = 119808
#define SM_MSK  119808            // mask [40][128] f32 = 20480
#define SM_HX   140288            // h exchange [128][40] f32 = 20480
#define SM_BIAS 160768            // 512
#define SM_TOTAL 161280

__device__ __align__(16) unsigned char g_imgA[N_INST * NC * IMGA_C];  // 5.73 MB
__device__ __align__(16) unsigned char g_imgB[N_INST * NC * IMGB_C];  // 6.39 MB

// ===================== helpers =====================
__device__ __forceinline__ uint32_t smem_u32(const void* p) {
    return (uint32_t)__cvta_generic_to_shared(p);
}
__device__ __forceinline__ void cp16(uint32_t smem_dst, const void* gmem_src) {
    asm volatile("cp.async.cg.shared.global [%0], [%1], 16;" :: "r"(smem_dst), "l"(gmem_src) : "memory");
}
#define CP_COMMIT() asm volatile("cp.async.commit_group;" ::: "memory")
__device__ __forceinline__ void cp_waitn(int n) {
    if (n == 0) asm volatile("cp.async.wait_group 0;" ::: "memory");
    else        asm volatile("cp.async.wait_group 1;" ::: "memory");
}
__device__ __forceinline__ void stageN(uint32_t dst, const unsigned char* src, int bytes, int tid) {
    for (int o = tid * 16; o < bytes; o += NTHR * 16) cp16(dst + o, src + o);
}
// bf16 MMA m16n8k16, fp32 accum
__device__ __forceinline__ void mma_bf16(float* d, const uint32_t* a, uint32_t b0, uint32_t b1) {
    asm volatile("mma.sync.aligned.m16n8k16.row.col.f32.bf16.bf16.f32 "
                 "{%0,%1,%2,%3},{%4,%5,%6,%7},{%8,%9},{%0,%1,%2,%3};"
                 : "+f"(d[0]), "+f"(d[1]), "+f"(d[2]), "+f"(d[3])
                 : "r"(a[0]), "r"(a[1]), "r"(a[2]), "r"(a[3]), "r"(b0), "r"(b1));
}
__device__ __forceinline__ uint32_t pack_bf2(float a, float b) {
    __nv_bfloat162 t = __floats2bfloat162_rn(a, b);   // x -> low half
    return *reinterpret_cast<uint32_t*>(&t);
}
__device__ __forceinline__ void split_pair(float a, float b, uint32_t& hi, uint32_t& lo) {
    const __nv_bfloat16 ah = __float2bfloat16(a), bh = __float2bfloat16(b);
    hi = pack_bf2(a, b);
    lo = pack_bf2(a - __bfloat162float(ah), b - __bfloat162float(bh));
}
__device__ __forceinline__ uint4 frag_word(float v00, float v01, float v10, float v11) {
    uint4 w;
    uint32_t h0, l0, h1, l1;
    split_pair(v00, v01, h0, l0);
    split_pair(v10, v11, h1, l1);
    w.x = h0; w.y = h1; w.z = l0; w.w = l1;
    return w;
}

// ===================== Kernel 1: G -> fragment images =====================
__global__ __launch_bounds__(256)
void compute_G_kernel(const float* __restrict__ A, const float* __restrict__ Bp) {
    __shared__ float AsT[NM * N_FEAT];    // 4100, transposed [m][f]
    __shared__ float Bs[NM * N_HID];      // 1640, [m][h]
    __shared__ float sS[N_FEAT * N_HID];  // 4000
    const int ic = blockIdx.x;
    const float* Ap  = A  + (size_t)ic * N_FEAT * NM;
    const float* Bpp = Bp + (size_t)ic * NM * N_HID;
    uint4* iA = reinterpret_cast<uint4*>(g_imgA + (size_t)ic * IMGA_C);
    uint4* iB = reinterpret_cast<uint4*>(g_imgB + (size_t)ic * IMGB_C);

    for (int idx = threadIdx.x; idx < N_FEAT * NM; idx += blockDim.x) {
        const int f = idx / NM, m = idx % NM;
        AsT[m * N_FEAT + f] = Ap[idx];
    }
    for (int idx = threadIdx.x; idx < NM * N_HID; idx += blockDim.x) Bs[idx] = Bpp[idx];
    __syncthreads();

    // 2x2 micro-tiles: 50 f-pairs x 20 h-pairs = 1000 tiles
    for (int t = threadIdx.x; t < 1000; t += blockDim.x) {
        const int fp = t / 20, hp = t % 20;
        float a00 = 0.f, a01 = 0.f, a10 = 0.f, a11 = 0.f;
#pragma unroll
        for (int m = 0; m < NM; m++) {
            const float2 a = *reinterpret_cast<const float2*>(&AsT[m * N_FEAT + fp * 2]);
            const float2 b = *reinterpret_cast<const float2*>(&Bs[m * N_HID + hp * 2]);
            a00 = fmaf(a.x, b.x, a00); a01 = fmaf(a.x, b.y, a01);
            a10 = fmaf(a.y, b.x, a10); a11 = fmaf(a.y, b.y, a11);
        }
        *reinterpret_cast<float2*>(&sS[(fp * 2)     * N_HID + hp * 2]) = make_float2(a00, a01);
        *reinterpret_cast<float2*>(&sS[(fp * 2 + 1) * N_HID + hp * 2]) = make_float2(a10, a11);
    }
    __syncthreads();

    // phase A image: B operand [k=f][n=h]
    for (int widx = threadIdx.x; widx < 7 * 5 * 32; widx += blockDim.x) {
        const int kst = widx / 160, rem = widx % 160;
        const int nt = rem / 32, T = rem % 32;
        const int q = T & 3, tr = T >> 2;
        const int n = nt * 8 + tr;
        float v[2][2];
#pragma unroll
        for (int half = 0; half < 2; half++)
#pragma unroll
            for (int lo = 0; lo < 2; lo++) {
                const int f = kst * 16 + q * 2 + half * 8 + lo;
                v[half][lo] = (f < N_FEAT) ? sS[f * N_HID + n] : 0.f;
            }
        iA[widx] = frag_word(v[0][0], v[0][1], v[1][0], v[1][1]);
    }
    // phase B image: B operand [k=h][n=f]
    for (int widx = threadIdx.x; widx < 3 * 13 * 32; widx += blockDim.x) {
        const int kst = widx / 416, rem = widx % 416;
        const int nt = rem / 32, T = rem % 32;
        const int q = T & 3, tr = T >> 2;
        const int f = nt * 8 + tr;
        float v[2][2];
#pragma unroll
        for (int half = 0; half < 2; half++)
#pragma unroll
            for (int lo = 0; lo < 2; lo++) {
                const int h = kst * 16 + q * 2 + half * 8 + lo;
                v[half][lo] = (f < N_FEAT && h < N_HID) ? sS[f * N_HID + h] : 0.f;
            }
        iB[widx] = frag_word(v[0][0], v[0][1], v[1][0], v[1][1]);
    }
}

// ===================== Kernel 2: fused main =====================
__global__ __launch_bounds__(NTHR)
void tmsspd_main_kernel(const float* __restrict__ x, const float* __restrict__ mask,
                        const float* __restrict__ bfin, float* __restrict__ out) {
    extern __shared__ char smem[];
    const uint32_t sb_ring = smem_u32(smem) + SM_RING;
    float* mskS  = reinterpret_cast<float*>(smem + SM_MSK);
    float* hX    = reinterpret_cast<float*>(smem + SM_HX);
    float* biasS = reinterpret_cast<float*>(smem + SM_BIAS);

    const int i   = blockIdx.y;
    const int b0  = blockIdx.x * 128;
    const int tid = threadIdx.x;
    const int w   = tid >> 5;
    const int T   = tid & 31;
    const int q   = T & 3;
    const int tr  = T >> 2;
    const int r0  = w * 16 + tr;
    const int r1  = r0 + 8;

    const unsigned char* imgA = g_imgA + (size_t)(i * NC) * IMGA_C;
    const unsigned char* imgB = g_imgB + (size_t)(i * NC) * IMGB_C;

    // prologue: stage A pairs 0,1 into slots 0,1
    stageN(sb_ring,               imgA,         SLOTA, tid); CP_COMMIT();
    stageN(sb_ring + RING_STRIDE, imgA + SLOTA, SLOTA, tid); CP_COMMIT();

    for (int idx = tid; idx < 128 * NC; idx += NTHR) {
        const int r = idx / NC, c = idx % NC;
        mskS[c * 128 + r] = mask[((size_t)(b0 + r) * N_INST + i) * NC + c];
    }
    if (tid < N_FEAT) biasS[tid] = bfin[i * N_FEAT + tid];

    // X fragments from gmem (rows r0/r1, bf16 split), K padded to 112
    uint32_t xhi[7][4], xlo[7][4];
    {
        const float* xr0 = x + ((size_t)(b0 + r0) * N_INST + i) * N_FEAT;
        const float* xr1 = x + ((size_t)(b0 + r1) * N_INST + i) * N_FEAT;
#pragma unroll
        for (int kst = 0; kst < 7; kst++) {
#pragma unroll
            for (int half = 0; half < 2; half++) {
                const int kk = kst * 16 + q * 2 + half * 8;
                float2 v0 = make_float2(0.f, 0.f), v1 = make_float2(0.f, 0.f);
                if (kk < N_FEAT) {
                    v0 = *reinterpret_cast<const float2*>(xr0 + kk);
                    v1 = *reinterpret_cast<const float2*>(xr1 + kk);
                }
                split_pair(v0.x, v0.y, xhi[kst][half * 2],     xlo[kst][half * 2]);
                split_pair(v1.x, v1.y, xhi[kst][half * 2 + 1], xlo[kst][half * 2 + 1]);
            }
        }
    }

    // ======================= Phase A (20 pair-iterations, 3-slot ring) =======================
    float hacc[5][4];
#pragma unroll
    for (int nt = 0; nt < 5; nt++)
#pragma unroll
        for (int j = 0; j < 4; j++) hacc[nt][j] = 0.f;

    for (int cp = 0; cp < 20; cp++) {
        cp_waitn(cp < 19 ? 1 : 0);          // this thread's copies for pair cp done
        __syncthreads();                    // all threads' copies visible; prev computes done
        if (cp + 2 <= 19) {                 // slot (cp+2)%3 held pair cp-1: consumed by all
            stageN(sb_ring + ((cp + 2) % 3) * RING_STRIDE,
                   imgA + (size_t)(cp + 2) * SLOTA, SLOTA, tid);
            CP_COMMIT();
        }

        const char* base = smem + SM_RING + (cp % 3) * RING_STRIDE;
#pragma unroll
        for (int cc = 0; cc < 2; cc++) {
            const int c = 2 * cp + cc;
            const char* buf = base + cc * IMGA_C;
            float d[5][4];
#pragma unroll
            for (int nt = 0; nt < 5; nt++)
#pragma unroll
                for (int j = 0; j < 4; j++) d[nt][j] = 0.f;

#pragma unroll
            for (int kst = 0; kst < 7; kst++) {
                uint4 wv[5];
#pragma unroll
                for (int nt = 0; nt < 5; nt++)
                    wv[nt] = *reinterpret_cast<const uint4*>(buf + (((kst * 5 + nt) * 32 + T) << 4));
                // term-major, nt-inner: same-accumulator MMAs are 5 apart
#pragma unroll
                for (int nt = 0; nt < 5; nt++) mma_bf16(d[nt], xhi[kst], wv[nt].x, wv[nt].y);
#pragma unroll
                for (int nt = 0; nt < 5; nt++) mma_bf16(d[nt], xhi[kst], wv[nt].z, wv[nt].w);
#pragma unroll
                for (int nt = 0; nt < 5; nt++) mma_bf16(d[nt], xlo[kst], wv[nt].x, wv[nt].y);
            }
            const float m0 = mskS[c * 128 + r0];
            const float m1 = mskS[c * 128 + r1];
#pragma unroll
            for (int nt = 0; nt < 5; nt++) {
                hacc[nt][0] = fmaf(m0, d[nt][0], hacc[nt][0]);
                hacc[nt][1] = fmaf(m0, d[nt][1], hacc[nt][1]);
                hacc[nt][2] = fmaf(m1, d[nt][2], hacc[nt][2]);
                hacc[nt][3] = fmaf(m1, d[nt][3], hacc[nt][3]);
            }
        }
    }

    // h exchange (warp-local)
#pragma unroll
    for (int nt = 0; nt < 5; nt++) {
        const int col = nt * 8 + q * 2;
        hX[r0 * N_HID + col]     = hacc[nt][0];
        hX[r0 * N_HID + col + 1] = hacc[nt][1];
        hX[r1 * N_HID + col]     = hacc[nt][2];
        hX[r1 * N_HID + col + 1] = hacc[nt][3];
    }
    // B pair p -> slot (p+2)%3. B0->slot2 (A pair17, long consumed), B1->slot0 (A pair18, consumed
    // before every thread's A-iter-19 barrier, which all threads have passed).
    stageN(sb_ring + 2 * RING_STRIDE, imgB,         SLOTB, tid); CP_COMMIT();
    __syncwarp();

    uint32_t hh[3][4], hl[3][4];
#pragma unroll
    for (int kst = 0; kst < 3; kst++) {
#pragma unroll
        for (int half = 0; half < 2; half++) {
            const int kk = kst * 16 + q * 2 + half * 8;
            float2 v0 = make_float2(0.f, 0.f), v1 = make_float2(0.f, 0.f);
            if (kk < N_HID) {
                v0 = *reinterpret_cast<const float2*>(&hX[r0 * N_HID + kk]);
                v1 = *reinterpret_cast<const float2*>(&hX[r1 * N_HID + kk]);
            }
            split_pair(v0.x, v0.y, hh[kst][half * 2],     hl[kst][half * 2]);
            split_pair(v1.x, v1.y, hh[kst][half * 2 + 1], hl[kst][half * 2 + 1]);
        }
    }
    stageN(sb_ring, imgB + SLOTB, SLOTB, tid); CP_COMMIT();

    // ======================= Phase B (20 pair-iterations) =======================
    float oacc[13][4];
#pragma unroll
    for (int nt = 0; nt < 13; nt++)
#pragma unroll
        for (int j = 0; j < 4; j++) oacc[nt][j] = 0.f;

    for (int cp = 0; cp < 20; cp++) {
        cp_waitn(cp < 19 ? 1 : 0);
        __syncthreads();
        if (cp + 2 <= 19) {
            stageN(sb_ring + ((cp + 2 + 2) % 3) * RING_STRIDE,
                   imgB + (size_t)(cp + 2) * SLOTB, SLOTB, tid);
            CP_COMMIT();
        }

        const char* base = smem + SM_RING + ((cp + 2) % 3) * RING_STRIDE;
#pragma unroll
        for (int cc = 0; cc < 2; cc++) {
            const int c = 2 * cp + cc;
            const char* buf = base + cc * IMGB_C;
            const uint32_t keep0 = (mskS[c * 128 + r0] != 0.f) ? 0xFFFFFFFFu : 0u;
            const uint32_t keep1 = (mskS[c * 128 + r1] != 0.f) ? 0xFFFFFFFFu : 0u;

#pragma unroll
            for (int kst = 0; kst < 3; kst++) {
                uint32_t ah[4], al[4];
                ah[0] = hh[kst][0] & keep0; ah[1] = hh[kst][1] & keep1;
                ah[2] = hh[kst][2] & keep0; ah[3] = hh[kst][3] & keep1;
                al[0] = hl[kst][0] & keep0; al[1] = hl[kst][1] & keep1;
                al[2] = hl[kst][2] & keep0; al[3] = hl[kst][3] & keep1;

                // group 1: nt 0..6 (chain distance 7)
                {
                    uint4 wv[7];
#pragma unroll
                    for (int j = 0; j < 7; j++)
                        wv[j] = *reinterpret_cast<const uint4*>(buf + (((kst * 13 + j) * 32 + T) << 4));
#pragma unroll
                    for (int j = 0; j < 7; j++) mma_bf16(oacc[j], ah, wv[j].x, wv[j].y);
#pragma unroll
                    for (int j = 0; j < 7; j++) mma_bf16(oacc[j], ah, wv[j].z, wv[j].w);
#pragma unroll
                    for (int j = 0; j < 7; j++) mma_bf16(oacc[j], al, wv[j].x, wv[j].y);
                }
                // group 2: nt 7..12 (chain distance 6)
                {
                    uint4 wv[6];
#pragma unroll
                    for (int j = 0; j < 6; j++)
                        wv[j] = *reinterpret_cast<const uint4*>(buf + (((kst * 13 + 7 + j) * 32 + T) << 4));
#pragma unroll
                    for (int j = 0; j < 6; j++) mma_bf16(oacc[7 + j], ah, wv[j].x, wv[j].y);
#pragma unroll
                    for (int j = 0; j < 6; j++) mma_bf16(oacc[7 + j], ah, wv[j].z, wv[j].w);
#pragma unroll
                    for (int j = 0; j < 6; j++) mma_bf16(oacc[7 + j], al, wv[j].x, wv[j].y);
                }
            }
        }
    }

    // ======================= epilogue =======================
    float* o0 = out + ((size_t)(b0 + r0) * N_INST + i) * N_FEAT;
    float* o1 = out + ((size_t)(b0 + r1) * N_INST + i) * N_FEAT;
#pragma unroll
    for (int nt = 0; nt < 13; nt++) {
        const int col = nt * 8 + q * 2;
        if (col < N_FEAT) {
            const float2 bf = *reinterpret_cast<const float2*>(&biasS[col]);
            float2 a, b;
            a.x = fmaxf(oacc[nt][0] + bf.x, 0.f);
            a.y = fmaxf(oacc[nt][1] + bf.y, 0.f);
            b.x = fmaxf(oacc[nt][2] + bf.x, 0.f);
            b.y = fmaxf(oacc[nt][3] + bf.y, 0.f);
            *reinterpret_cast<float2*>(o0 + col) = a;
            *reinterpret_cast<float2*>(o1 + col) = b;
        }
    }
}

// ---------------------------------------------------------------------------
extern "C" void kernel_launch(void* const* d_in, const int* in_sizes, int n_in,
                              void* d_out, int out_size) {
    (void)in_sizes; (void)n_in; (void)out_size;
    const float* x    = (const float*)d_in[0];
    const float* mask = (const float*)d_in[1];
    const float* A    = (const float*)d_in[2];
    const float* Bp   = (const float*)d_in[3];
    const float* bfin = (const float*)d_in[4];
    float* out = (float*)d_out;

    cudaFuncSetAttribute(tmsspd_main_kernel,
                         cudaFuncAttributeMaxDynamicSharedMemorySize, SM_TOTAL);

    compute_G_kernel<<<N_INST * NC, 256>>>(A, Bp);

    dim3 grid(B_SZ / 128, N_INST);
    tmsspd_main_kernel<<<grid, NTHR, SM_TOTAL>>>(x, mask, bfin, out);
}

// round 10
// speedup vs baseline: 3.0071x; 1.0204x over previous
#include <cuda_runtime.h>
#include <cuda_bf16.h>
#include <cstdint>

#define B_SZ   2048
#define N_INST 8
#define N_FEAT 100
#define N_HID  40
#define NC     40
#define NM     41
#define NTHR   512

// fragment-image sizes (bytes) per (i,c); hi/lo interleaved per 16B word
#define IMGA_C 17920              // 7 kstep x 5 ntile x 32 thr x 16B
#define IMGB_C 19968              // 3 kstep x 13 ntile x 32 thr x 16B
#define SLOTA  (2*IMGA_C)         // two c's per ring slot
#define SLOTB  (2*IMGB_C)
#define RING_STRIDE 39936

// smem layout: per-group 2-slot rings, then shared tiles
#define SM_RING 0                 // 2 groups x 2 slots x 39936 = 159744
#define SM_MSK  159744            // mask [40][128] f32 = 20480
#define SM_HP   180224            // h partials: 2 x [128][40] f32 = 40960
#define SM_BIAS 221184            // 512
#define SM_TOTAL 221696

__device__ __align__(16) unsigned char g_imgA[N_INST * NC * IMGA_C];
__device__ __align__(16) unsigned char g_imgB[N_INST * NC * IMGB_C];

// ===================== helpers =====================
__device__ __forceinline__ uint32_t smem_u32(const void* p) {
    return (uint32_t)__cvta_generic_to_shared(p);
}
__device__ __forceinline__ void cp16(uint32_t smem_dst, const void* gmem_src) {
    asm volatile("cp.async.cg.shared.global [%0], [%1], 16;" :: "r"(smem_dst), "l"(gmem_src) : "memory");
}
#define CP_COMMIT() asm volatile("cp.async.commit_group;" ::: "memory")
__device__ __forceinline__ void cp_waitn(int n) {
    if (n == 0) asm volatile("cp.async.wait_group 0;" ::: "memory");
    else        asm volatile("cp.async.wait_group 1;" ::: "memory");
}
// group-local stage: 256 threads of this group
__device__ __forceinline__ void stageG(uint32_t dst, const unsigned char* src, int bytes, int tg) {
    for (int o = tg * 16; o < bytes; o += 256 * 16) cp16(dst + o, src + o);
}
#define BARG(id) asm volatile("bar.sync %0, 256;" :: "r"(id) : "memory")

__device__ __forceinline__ void mma_bf16(float* d, const uint32_t* a, uint32_t b0, uint32_t b1) {
    asm volatile("mma.sync.aligned.m16n8k16.row.col.f32.bf16.bf16.f32 "
                 "{%0,%1,%2,%3},{%4,%5,%6,%7},{%8,%9},{%0,%1,%2,%3};"
                 : "+f"(d[0]), "+f"(d[1]), "+f"(d[2]), "+f"(d[3])
                 : "r"(a[0]), "r"(a[1]), "r"(a[2]), "r"(a[3]), "r"(b0), "r"(b1));
}
__device__ __forceinline__ void mma_bf16_k8(float* d, uint32_t a0, uint32_t a1, uint32_t b0) {
    asm volatile("mma.sync.aligned.m16n8k8.row.col.f32.bf16.bf16.f32 "
                 "{%0,%1,%2,%3},{%4,%5},{%6},{%0,%1,%2,%3};"
                 : "+f"(d[0]), "+f"(d[1]), "+f"(d[2]), "+f"(d[3])
                 : "r"(a0), "r"(a1), "r"(b0));
}
__device__ __forceinline__ uint32_t pack_bf2(float a, float b) {
    __nv_bfloat162 t = __floats2bfloat162_rn(a, b);
    return *reinterpret_cast<uint32_t*>(&t);
}
__device__ __forceinline__ void split_pair(float a, float b, uint32_t& hi, uint32_t& lo) {
    const __nv_bfloat16 ah = __float2bfloat16(a), bh = __float2bfloat16(b);
    hi = pack_bf2(a, b);
    lo = pack_bf2(a - __bfloat162float(ah), b - __bfloat162float(bh));
}
__device__ __forceinline__ uint4 frag_word(float v00, float v01, float v10, float v11) {
    uint4 w;
    uint32_t h0, l0, h1, l1;
    split_pair(v00, v01, h0, l0);
    split_pair(v10, v11, h1, l1);
    w.x = h0; w.y = h1; w.z = l0; w.w = l1;
    return w;
}

// ===================== Kernel 1: G -> fragment images =====================
__global__ __launch_bounds__(256)
void compute_G_kernel(const float* __restrict__ A, const float* __restrict__ Bp) {
    __shared__ float AsT[NM * N_FEAT];
    __shared__ float Bs[NM * N_HID];
    __shared__ float sS[N_FEAT * N_HID];
    const int ic = blockIdx.x;
    const float* Ap  = A  + (size_t)ic * N_FEAT * NM;
    const float* Bpp = Bp + (size_t)ic * NM * N_HID;
    uint4* iA = reinterpret_cast<uint4*>(g_imgA + (size_t)ic * IMGA_C);
    uint4* iB = reinterpret_cast<uint4*>(g_imgB + (size_t)ic * IMGB_C);

    for (int idx = threadIdx.x; idx < N_FEAT * NM; idx += blockDim.x) {
        const int f = idx / NM, m = idx % NM;
        AsT[m * N_FEAT + f] = Ap[idx];
    }
    for (int idx = threadIdx.x; idx < NM * N_HID; idx += blockDim.x) Bs[idx] = Bpp[idx];
    __syncthreads();

    for (int t = threadIdx.x; t < 1000; t += blockDim.x) {
        const int fp = t / 20, hp = t % 20;
        float a00 = 0.f, a01 = 0.f, a10 = 0.f, a11 = 0.f;
#pragma unroll
        for (int m = 0; m < NM; m++) {
            const float2 a = *reinterpret_cast<const float2*>(&AsT[m * N_FEAT + fp * 2]);
            const float2 b = *reinterpret_cast<const float2*>(&Bs[m * N_HID + hp * 2]);
            a00 = fmaf(a.x, b.x, a00); a01 = fmaf(a.x, b.y, a01);
            a10 = fmaf(a.y, b.x, a10); a11 = fmaf(a.y, b.y, a11);
        }
        *reinterpret_cast<float2*>(&sS[(fp * 2)     * N_HID + hp * 2]) = make_float2(a00, a01);
        *reinterpret_cast<float2*>(&sS[(fp * 2 + 1) * N_HID + hp * 2]) = make_float2(a10, a11);
    }
    __syncthreads();

    for (int widx = threadIdx.x; widx < 7 * 5 * 32; widx += blockDim.x) {
        const int kst = widx / 160, rem = widx % 160;
        const int nt = rem / 32, T = rem % 32;
        const int q = T & 3, tr = T >> 2;
        const int n = nt * 8 + tr;
        float v[2][2];
#pragma unroll
        for (int half = 0; half < 2; half++)
#pragma unroll
            for (int lo = 0; lo < 2; lo++) {
                const int f = kst * 16 + q * 2 + half * 8 + lo;
                v[half][lo] = (f < N_FEAT) ? sS[f * N_HID + n] : 0.f;
            }
        iA[widx] = frag_word(v[0][0], v[0][1], v[1][0], v[1][1]);
    }
    for (int widx = threadIdx.x; widx < 3 * 13 * 32; widx += blockDim.x) {
        const int kst = widx / 416, rem = widx % 416;
        const int nt = rem / 32, T = rem % 32;
        const int q = T & 3, tr = T >> 2;
        const int f = nt * 8 + tr;
        float v[2][2];
#pragma unroll
        for (int half = 0; half < 2; half++)
#pragma unroll
            for (int lo = 0; lo < 2; lo++) {
                const int h = kst * 16 + q * 2 + half * 8 + lo;
                v[half][lo] = (f < N_FEAT && h < N_HID) ? sS[f * N_HID + h] : 0.f;
            }
        iB[widx] = frag_word(v[0][0], v[0][1], v[1][0], v[1][1]);
    }
}

// ===================== Kernel 2: fused main, 512 thr, c-split =====================
__global__ __launch_bounds__(NTHR)
void tmsspd_main_kernel(const float* __restrict__ x, const float* __restrict__ mask,
                        const float* __restrict__ bfin, float* __restrict__ out) {
    extern __shared__ char smem[];
    float* mskS  = reinterpret_cast<float*>(smem + SM_MSK);
    float* hp0   = reinterpret_cast<float*>(smem + SM_HP);          // [128][40]
    float* hp1   = hp0 + 128 * N_HID;
    float* biasS = reinterpret_cast<float*>(smem + SM_BIAS);

    const int i   = blockIdx.y;
    const int b0  = blockIdx.x * 128;
    const int tid = threadIdx.x;
    const int w   = tid >> 5;
    const int T   = tid & 31;
    const int g   = w >> 3;            // c-group
    const int tg  = tid & 255;
    const int wg  = w & 7;
    const int q   = T & 3;
    const int tr  = T >> 2;
    const int r0  = wg * 16 + tr;
    const int r1  = r0 + 8;
    const int barid = 1 + g;

    const uint32_t rb = smem_u32(smem) + SM_RING + (uint32_t)g * (2 * RING_STRIDE);
    const char* rbp = smem + SM_RING + g * (2 * RING_STRIDE);

    const unsigned char* imgAg = g_imgA + (size_t)(i * NC) * IMGA_C + (size_t)(g * 10) * SLOTA;
    const unsigned char* imgBg = g_imgB + (size_t)(i * NC) * IMGB_C + (size_t)(g * 10) * SLOTB;

    // prologue: stage this group's A pair 0 into slot 0
    stageG(rb, imgAg, SLOTA, tg); CP_COMMIT();

    for (int idx = tid; idx < 128 * NC; idx += NTHR) {
        const int r = idx / NC, c = idx % NC;
        mskS[c * 128 + r] = mask[((size_t)(b0 + r) * N_INST + i) * NC + c];
    }
    if (tid < N_FEAT) biasS[tid] = bfin[i * N_FEAT + tid];

    // X fragments: kst 0..5 full k16, kst6 k8 (f 96..103)
    uint32_t xhi[6][4], xlo[6][4], xh6[2], xl6[2];
    {
        const float* xr0 = x + ((size_t)(b0 + r0) * N_INST + i) * N_FEAT;
        const float* xr1 = x + ((size_t)(b0 + r1) * N_INST + i) * N_FEAT;
#pragma unroll
        for (int kst = 0; kst < 6; kst++) {
#pragma unroll
            for (int half = 0; half < 2; half++) {
                const int kk = kst * 16 + q * 2 + half * 8;   // <= 94, always in-bounds
                const float2 v0 = *reinterpret_cast<const float2*>(xr0 + kk);
                const float2 v1 = *reinterpret_cast<const float2*>(xr1 + kk);
                split_pair(v0.x, v0.y, xhi[kst][half * 2],     xlo[kst][half * 2]);
                split_pair(v1.x, v1.y, xhi[kst][half * 2 + 1], xlo[kst][half * 2 + 1]);
            }
        }
        const int kk = 96 + q * 2;
        float2 v0 = make_float2(0.f, 0.f), v1 = make_float2(0.f, 0.f);
        if (kk < N_FEAT) {
            v0 = *reinterpret_cast<const float2*>(xr0 + kk);
            v1 = *reinterpret_cast<const float2*>(xr1 + kk);
        }
        split_pair(v0.x, v0.y, xh6[0], xl6[0]);
        split_pair(v1.x, v1.y, xh6[1], xl6[1]);
    }
    __syncthreads();   // mask/bias visible

    // ======================= Phase A: 10 pair-iterations per group =======================
    float hacc[5][4];
#pragma unroll
    for (int nt = 0; nt < 5; nt++)
#pragma unroll
        for (int j = 0; j < 4; j++) hacc[nt][j] = 0.f;

    for (int cp = 0; cp < 10; cp++) {
        BARG(barid);                        // other slot's consumers done
        if (cp + 1 < 10) {
            stageG(rb + ((cp + 1) & 1) * RING_STRIDE,
                   imgAg + (size_t)(cp + 1) * SLOTA, SLOTA, tg);
            CP_COMMIT();
        }
        cp_waitn(cp + 1 < 10 ? 1 : 0);
        BARG(barid);                        // slot cp&1 visible to group

        const char* base = rbp + (cp & 1) * RING_STRIDE;
#pragma unroll
        for (int cc = 0; cc < 2; cc++) {
            const int c = 2 * (g * 10 + cp) + cc;
            const char* buf = base + cc * IMGA_C;
            float d[5][4];
#pragma unroll
            for (int nt = 0; nt < 5; nt++)
#pragma unroll
                for (int j = 0; j < 4; j++) d[nt][j] = 0.f;

#pragma unroll
            for (int kst = 0; kst < 6; kst++) {
                uint4 wv[5];
#pragma unroll
                for (int nt = 0; nt < 5; nt++)
                    wv[nt] = *reinterpret_cast<const uint4*>(buf + (((kst * 5 + nt) * 32 + T) << 4));
#pragma unroll
                for (int nt = 0; nt < 5; nt++) mma_bf16(d[nt], xhi[kst], wv[nt].x, wv[nt].y);
#pragma unroll
                for (int nt = 0; nt < 5; nt++) mma_bf16(d[nt], xhi[kst], wv[nt].z, wv[nt].w);
#pragma unroll
                for (int nt = 0; nt < 5; nt++) mma_bf16(d[nt], xlo[kst], wv[nt].x, wv[nt].y);
            }
            {   // kst 6: k8 (f 96..103)
                uint4 wv[5];
#pragma unroll
                for (int nt = 0; nt < 5; nt++)
                    wv[nt] = *reinterpret_cast<const uint4*>(buf + (((6 * 5 + nt) * 32 + T) << 4));
#pragma unroll
                for (int nt = 0; nt < 5; nt++) mma_bf16_k8(d[nt], xh6[0], xh6[1], wv[nt].x);
#pragma unroll
                for (int nt = 0; nt < 5; nt++) mma_bf16_k8(d[nt], xh6[0], xh6[1], wv[nt].z);
#pragma unroll
                for (int nt = 0; nt < 5; nt++) mma_bf16_k8(d[nt], xl6[0], xl6[1], wv[nt].x);
            }
            const float m0 = mskS[c * 128 + r0];
            const float m1 = mskS[c * 128 + r1];
#pragma unroll
            for (int nt = 0; nt < 5; nt++) {
                hacc[nt][0] = fmaf(m0, d[nt][0], hacc[nt][0]);
                hacc[nt][1] = fmaf(m0, d[nt][1], hacc[nt][1]);
                hacc[nt][2] = fmaf(m1, d[nt][2], hacc[nt][2]);
                hacc[nt][3] = fmaf(m1, d[nt][3], hacc[nt][3]);
            }
        }
    }

    // write group partial h
    {
        float* hp = g ? hp1 : hp0;
#pragma unroll
        for (int nt = 0; nt < 5; nt++) {
            const int col = nt * 8 + q * 2;
            *reinterpret_cast<float2*>(&hp[r0 * N_HID + col]) = make_float2(hacc[nt][0], hacc[nt][1]);
            *reinterpret_cast<float2*>(&hp[r1 * N_HID + col]) = make_float2(hacc[nt][2], hacc[nt][3]);
        }
    }
    // stage this group's B pair 0 into slot 0 (its A data long consumed)
    stageG(rb, imgBg, SLOTB, tg); CP_COMMIT();
    __syncthreads();   // both partials visible

    // h fragments from summed partials: kst 0,1 k16; kst2 k8 (h 32..39)
    uint32_t hh[2][4], hl[2][4], hh2[2], hl2[2];
#pragma unroll
    for (int kst = 0; kst < 2; kst++) {
#pragma unroll
        for (int half = 0; half < 2; half++) {
            const int kk = kst * 16 + q * 2 + half * 8;
            const float2 a0 = *reinterpret_cast<const float2*>(&hp0[r0 * N_HID + kk]);
            const float2 b0v = *reinterpret_cast<const float2*>(&hp1[r0 * N_HID + kk]);
            const float2 a1 = *reinterpret_cast<const float2*>(&hp0[r1 * N_HID + kk]);
            const float2 b1v = *reinterpret_cast<const float2*>(&hp1[r1 * N_HID + kk]);
            split_pair(a0.x + b0v.x, a0.y + b0v.y, hh[kst][half * 2],     hl[kst][half * 2]);
            split_pair(a1.x + b1v.x, a1.y + b1v.y, hh[kst][half * 2 + 1], hl[kst][half * 2 + 1]);
        }
    }
    {
        const int kk = 32 + q * 2;
        const float2 a0 = *reinterpret_cast<const float2*>(&hp0[r0 * N_HID + kk]);
        const float2 b0v = *reinterpret_cast<const float2*>(&hp1[r0 * N_HID + kk]);
        const float2 a1 = *reinterpret_cast<const float2*>(&hp0[r1 * N_HID + kk]);
        const float2 b1v = *reinterpret_cast<const float2*>(&hp1[r1 * N_HID + kk]);
        split_pair(a0.x + b0v.x, a0.y + b0v.y, hh2[0], hl2[0]);
        split_pair(a1.x + b1v.x, a1.y + b1v.y, hh2[1], hl2[1]);
    }

    // ======================= Phase B: 10 pair-iterations per group =======================
    float oacc[13][4];
#pragma unroll
    for (int nt = 0; nt < 13; nt++)
#pragma unroll
        for (int j = 0; j < 4; j++) oacc[nt][j] = 0.f;

    for (int cp = 0; cp < 10; cp++) {
        BARG(barid);
        if (cp + 1 < 10) {
            stageG(rb + ((cp + 1) & 1) * RING_STRIDE,
                   imgBg + (size_t)(cp + 1) * SLOTB, SLOTB, tg);
            CP_COMMIT();
        }
        cp_waitn(cp + 1 < 10 ? 1 : 0);
        BARG(barid);

        const char* base = rbp + (cp & 1) * RING_STRIDE;
#pragma unroll
        for (int cc = 0; cc < 2; cc++) {
            const int c = 2 * (g * 10 + cp) + cc;
            const char* buf = base + cc * IMGB_C;
            const uint32_t keep0 = (mskS[c * 128 + r0] != 0.f) ? 0xFFFFFFFFu : 0u;
            const uint32_t keep1 = (mskS[c * 128 + r1] != 0.f) ? 0xFFFFFFFFu : 0u;

#pragma unroll
            for (int kst = 0; kst < 2; kst++) {            // k16 steps
                uint32_t ah[4], al[4];
                ah[0] = hh[kst][0] & keep0; ah[1] = hh[kst][1] & keep1;
                ah[2] = hh[kst][2] & keep0; ah[3] = hh[kst][3] & keep1;
                al[0] = hl[kst][0] & keep0; al[1] = hl[kst][1] & keep1;
                al[2] = hl[kst][2] & keep0; al[3] = hl[kst][3] & keep1;
                {
                    uint4 wv[7];
#pragma unroll
                    for (int j = 0; j < 7; j++)
                        wv[j] = *reinterpret_cast<const uint4*>(buf + (((kst * 13 + j) * 32 + T) << 4));
#pragma unroll
                    for (int j = 0; j < 7; j++) mma_bf16(oacc[j], ah, wv[j].x, wv[j].y);
#pragma unroll
                    for (int j = 0; j < 7; j++) mma_bf16(oacc[j], ah, wv[j].z, wv[j].w);
#pragma unroll
                    for (int j = 0; j < 7; j++) mma_bf16(oacc[j], al, wv[j].x, wv[j].y);
                }
                {
                    uint4 wv[6];
#pragma unroll
                    for (int j = 0; j < 6; j++)
                        wv[j] = *reinterpret_cast<const uint4*>(buf + (((kst * 13 + 7 + j) * 32 + T) << 4));
#pragma unroll
                    for (int j = 0; j < 6; j++) mma_bf16(oacc[7 + j], ah, wv[j].x, wv[j].y);
#pragma unroll
                    for (int j = 0; j < 6; j++) mma_bf16(oacc[7 + j], ah, wv[j].z, wv[j].w);
#pragma unroll
                    for (int j = 0; j < 6; j++) mma_bf16(oacc[7 + j], al, wv[j].x, wv[j].y);
                }
            }
            {   // kst 2: k8 (h 32..39)
                const uint32_t a0 = hh2[0] & keep0, a1 = hh2[1] & keep1;
                const uint32_t c0 = hl2[0] & keep0, c1 = hl2[1] & keep1;
                {
                    uint4 wv[7];
#pragma unroll
                    for (int j = 0; j < 7; j++)
                        wv[j] = *reinterpret_cast<const uint4*>(buf + (((2 * 13 + j) * 32 + T) << 4));
#pragma unroll
                    for (int j = 0; j < 7; j++) mma_bf16_k8(oacc[j], a0, a1, wv[j].x);
#pragma unroll
                    for (int j = 0; j < 7; j++) mma_bf16_k8(oacc[j], a0, a1, wv[j].z);
#pragma unroll
                    for (int j = 0; j < 7; j++) mma_bf16_k8(oacc[j], c0, c1, wv[j].x);
                }
                {
                    uint4 wv[6];
#pragma unroll
                    for (int j = 0; j < 6; j++)
                        wv[j] = *reinterpret_cast<const uint4*>(buf + (((2 * 13 + 7 + j) * 32 + T) << 4));
#pragma unroll
                    for (int j = 0; j < 6; j++) mma_bf16_k8(oacc[7 + j], a0, a1, wv[j].x);
#pragma unroll
                    for (int j = 0; j < 6; j++) mma_bf16_k8(oacc[7 + j], a0, a1, wv[j].z);
#pragma unroll
                    for (int j = 0; j < 6; j++) mma_bf16_k8(oacc[7 + j], c0, c1, wv[j].x);
                }
            }
        }
    }

    // ======================= cross-group reduce + epilogue =======================
    float* stash = reinterpret_cast<float*>(smem);   // [128][104], ring dead
    __syncthreads();
    if (g == 1) {
#pragma unroll
        for (int nt = 0; nt < 13; nt++) {
            const int col = nt * 8 + q * 2;
            *reinterpret_cast<float2*>(&stash[r0 * 104 + col]) = make_float2(oacc[nt][0], oacc[nt][1]);
            *reinterpret_cast<float2*>(&stash[r1 * 104 + col]) = make_float2(oacc[nt][2], oacc[nt][3]);
        }
    }
    __syncthreads();
    if (g == 0) {
        float* o0 = out + ((size_t)(b0 + r0) * N_INST + i) * N_FEAT;
        float* o1 = out + ((size_t)(b0 + r1) * N_INST + i) * N_FEAT;
#pragma unroll
        for (int nt = 0; nt < 13; nt++) {
            const int col = nt * 8 + q * 2;
            if (col < N_FEAT) {
                const float2 s0 = *reinterpret_cast<const float2*>(&stash[r0 * 104 + col]);
                const float2 s1 = *reinterpret_cast<const float2*>(&stash[r1 * 104 + col]);
                const float2 bf = *reinterpret_cast<const float2*>(&biasS[col]);
                float2 a, b;
                a.x = fmaxf(oacc[nt][0] + s0.x + bf.x, 0.f);
                a.y = fmaxf(oacc[nt][1] + s0.y + bf.y, 0.f);
                b.x = fmaxf(oacc[nt][2] + s1.x + bf.x, 0.f);
                b.y = fmaxf(oacc[nt][3] + s1.y + bf.y, 0.f);
                *reinterpret_cast<float2*>(o0 + col) = a;
                *reinterpret_cast<float2*>(o1 + col) = b;
            }
        }
    }
}

// ---------------------------------------------------------------------------
extern "C" void kernel_launch(void* const* d_in, const int* in_sizes, int n_in,
                              void* d_out, int out_size) {
    (void)in_sizes; (void)n_in; (void)out_size;
    const float* x    = (const float*)d_in[0];
    const float* mask = (const float*)d_in[1];
    const float* A    = (const float*)d_in[2];
    const float* Bp   = (const float*)d_in[3];
    const float* bfin = (const float*)d_in[4];
    float* out = (float*)d_out;

    cudaFuncSetAttribute(tmsspd_main_kernel,
                         cudaFuncAttributeMaxDynamicSharedMemorySize, SM_TOTAL);

    compute_G_kernel<<<N_INST * NC, 256>>>(A, Bp);

    dim3 grid(B_SZ / 128, N_INST);
    tmsspd_main_kernel<<<grid, NTHR, SM_TOTAL>>>(x, mask, bfin, out);
}

// round 11
// speedup vs baseline: 3.0088x; 1.0006x over previous
#include <cuda_runtime.h>
#include <cuda_bf16.h>
#include <cstdint>

#define B_SZ   2048
#define N_INST 8
#define N_FEAT 100
#define N_HID  40
#define NC     40
#define NM     41
#define NTHR   512

// fragment-image sizes (bytes) per (i,c); hi/lo interleaved per 16B word
#define IMGA_C 17920              // 7 kstep x 5 ntile x 32 thr x 16B
#define IMGB_C 19968              // 3 kstep x 13 ntile x 32 thr x 16B
#define SLOTA  (2*IMGA_C)         // two c's per ring slot
#define SLOTB  (2*IMGB_C)
#define RING_STRIDE 39936

// smem layout: per-group 2-slot rings, then shared tiles
#define SM_RING 0                 // 2 groups x 2 slots x 39936 = 159744
#define SM_MSK  159744            // mask [40][128] f32 = 20480
#define SM_HP   180224            // h partials: 2 x [128][40] f32 = 40960
#define SM_BIAS 221184            // 512
#define SM_TOTAL 221696

__device__ __align__(16) unsigned char g_imgA[N_INST * NC * IMGA_C];
__device__ __align__(16) unsigned char g_imgB[N_INST * NC * IMGB_C];

// ===================== helpers =====================
__device__ __forceinline__ uint32_t smem_u32(const void* p) {
    return (uint32_t)__cvta_generic_to_shared(p);
}
__device__ __forceinline__ void cp16(uint32_t smem_dst, const void* gmem_src) {
    asm volatile("cp.async.cg.shared.global [%0], [%1], 16;" :: "r"(smem_dst), "l"(gmem_src) : "memory");
}
#define CP_COMMIT() asm volatile("cp.async.commit_group;" ::: "memory")
__device__ __forceinline__ void cp_waitn(int n) {
    if (n == 0) asm volatile("cp.async.wait_group 0;" ::: "memory");
    else        asm volatile("cp.async.wait_group 1;" ::: "memory");
}
// group-local stage: 256 threads of this group
__device__ __forceinline__ void stageG(uint32_t dst, const unsigned char* src, int bytes, int tg) {
    for (int o = tg * 16; o < bytes; o += 256 * 16) cp16(dst + o, src + o);
}
#define BARG(id) asm volatile("bar.sync %0, 256;" :: "r"(id) : "memory")

__device__ __forceinline__ void mma_bf16(float* d, const uint32_t* a, uint32_t b0, uint32_t b1) {
    asm volatile("mma.sync.aligned.m16n8k16.row.col.f32.bf16.bf16.f32 "
                 "{%0,%1,%2,%3},{%4,%5,%6,%7},{%8,%9},{%0,%1,%2,%3};"
                 : "+f"(d[0]), "+f"(d[1]), "+f"(d[2]), "+f"(d[3])
                 : "r"(a[0]), "r"(a[1]), "r"(a[2]), "r"(a[3]), "r"(b0), "r"(b1));
}
__device__ __forceinline__ void mma_bf16_k8(float* d, uint32_t a0, uint32_t a1, uint32_t b0) {
    asm volatile("mma.sync.aligned.m16n8k8.row.col.f32.bf16.bf16.f32 "
                 "{%0,%1,%2,%3},{%4,%5},{%6},{%0,%1,%2,%3};"
                 : "+f"(d[0]), "+f"(d[1]), "+f"(d[2]), "+f"(d[3])
                 : "r"(a0), "r"(a1), "r"(b0));
}
__device__ __forceinline__ uint32_t pack_bf2(float a, float b) {
    __nv_bfloat162 t = __floats2bfloat162_rn(a, b);
    return *reinterpret_cast<uint32_t*>(&t);
}
__device__ __forceinline__ void split_pair(float a, float b, uint32_t& hi, uint32_t& lo) {
    const __nv_bfloat16 ah = __float2bfloat16(a), bh = __float2bfloat16(b);
    hi = pack_bf2(a, b);
    lo = pack_bf2(a - __bfloat162float(ah), b - __bfloat162float(bh));
}
__device__ __forceinline__ uint4 frag_word(float v00, float v01, float v10, float v11) {
    uint4 w;
    uint32_t h0, l0, h1, l1;
    split_pair(v00, v01, h0, l0);
    split_pair(v10, v11, h1, l1);
    w.x = h0; w.y = h1; w.z = l0; w.w = l1;
    return w;
}

// ===================== Kernel 1: G -> fragment images =====================
__global__ __launch_bounds__(256)
void compute_G_kernel(const float* __restrict__ A, const float* __restrict__ Bp) {
    __shared__ float AsT[NM * N_FEAT];
    __shared__ float Bs[NM * N_HID];
    __shared__ float sS[N_FEAT * N_HID];
    const int ic = blockIdx.x;
    const float* Ap  = A  + (size_t)ic * N_FEAT * NM;
    const float* Bpp = Bp + (size_t)ic * NM * N_HID;
    uint4* iA = reinterpret_cast<uint4*>(g_imgA + (size_t)ic * IMGA_C);
    uint4* iB = reinterpret_cast<uint4*>(g_imgB + (size_t)ic * IMGB_C);

    for (int idx = threadIdx.x; idx < N_FEAT * NM; idx += blockDim.x) {
        const int f = idx / NM, m = idx % NM;
        AsT[m * N_FEAT + f] = Ap[idx];
    }
    for (int idx = threadIdx.x; idx < NM * N_HID; idx += blockDim.x) Bs[idx] = Bpp[idx];
    __syncthreads();

    for (int t = threadIdx.x; t < 1000; t += blockDim.x) {
        const int fp = t / 20, hp = t % 20;
        float a00 = 0.f, a01 = 0.f, a10 = 0.f, a11 = 0.f;
#pragma unroll
        for (int m = 0; m < NM; m++) {
            const float2 a = *reinterpret_cast<const float2*>(&AsT[m * N_FEAT + fp * 2]);
            const float2 b = *reinterpret_cast<const float2*>(&Bs[m * N_HID + hp * 2]);
            a00 = fmaf(a.x, b.x, a00); a01 = fmaf(a.x, b.y, a01);
            a10 = fmaf(a.y, b.x, a10); a11 = fmaf(a.y, b.y, a11);
        }
        *reinterpret_cast<float2*>(&sS[(fp * 2)     * N_HID + hp * 2]) = make_float2(a00, a01);
        *reinterpret_cast<float2*>(&sS[(fp * 2 + 1) * N_HID + hp * 2]) = make_float2(a10, a11);
    }
    __syncthreads();

    for (int widx = threadIdx.x; widx < 7 * 5 * 32; widx += blockDim.x) {
        const int kst = widx / 160, rem = widx % 160;
        const int nt = rem / 32, T = rem % 32;
        const int q = T & 3, tr = T >> 2;
        const int n = nt * 8 + tr;
        float v[2][2];
#pragma unroll
        for (int half = 0; half < 2; half++)
#pragma unroll
            for (int lo = 0; lo < 2; lo++) {
                const int f = kst * 16 + q * 2 + half * 8 + lo;
                v[half][lo] = (f < N_FEAT) ? sS[f * N_HID + n] : 0.f;
            }
        iA[widx] = frag_word(v[0][0], v[0][1], v[1][0], v[1][1]);
    }
    for (int widx = threadIdx.x; widx < 3 * 13 * 32; widx += blockDim.x) {
        const int kst = widx / 416, rem = widx % 416;
        const int nt = rem / 32, T = rem % 32;
        const int q = T & 3, tr = T >> 2;
        const int f = nt * 8 + tr;
        float v[2][2];
#pragma unroll
        for (int half = 0; half < 2; half++)
#pragma unroll
            for (int lo = 0; lo < 2; lo++) {
                const int h = kst * 16 + q * 2 + half * 8 + lo;
                v[half][lo] = (f < N_FEAT && h < N_HID) ? sS[f * N_HID + h] : 0.f;
            }
        iB[widx] = frag_word(v[0][0], v[0][1], v[1][0], v[1][1]);
    }
}

// ===================== Kernel 2: fused main, 512 thr, c-split =====================
__global__ __launch_bounds__(NTHR)
void tmsspd_main_kernel(const float* __restrict__ x, const float* __restrict__ mask,
                        const float* __restrict__ bfin, float* __restrict__ out) {
    extern __shared__ char smem[];
    float* mskS  = reinterpret_cast<float*>(smem + SM_MSK);
    float* hp0   = reinterpret_cast<float*>(smem + SM_HP);          // [128][40]
    float* hp1   = hp0 + 128 * N_HID;
    float* biasS = reinterpret_cast<float*>(smem + SM_BIAS);

    const int i   = blockIdx.y;
    const int b0  = blockIdx.x * 128;
    const int tid = threadIdx.x;
    const int w   = tid >> 5;
    const int T   = tid & 31;
    const int g   = w >> 3;            // c-group
    const int tg  = tid & 255;
    const int wg  = w & 7;
    const int q   = T & 3;
    const int tr  = T >> 2;
    const int r0  = wg * 16 + tr;
    const int r1  = r0 + 8;
    const int barid = 1 + g;

    const uint32_t rb = smem_u32(smem) + SM_RING + (uint32_t)g * (2 * RING_STRIDE);
    const char* rbp = smem + SM_RING + g * (2 * RING_STRIDE);

    const unsigned char* imgAg = g_imgA + (size_t)(i * NC) * IMGA_C + (size_t)(g * 10) * SLOTA;
    const unsigned char* imgBg = g_imgB + (size_t)(i * NC) * IMGB_C + (size_t)(g * 10) * SLOTB;

    // prologue: stage this group's A pair 0 into slot 0
    stageG(rb, imgAg, SLOTA, tg); CP_COMMIT();

    for (int idx = tid; idx < 128 * NC; idx += NTHR) {
        const int r = idx / NC, c = idx % NC;
        mskS[c * 128 + r] = mask[((size_t)(b0 + r) * N_INST + i) * NC + c];
    }
    if (tid < N_FEAT) biasS[tid] = bfin[i * N_FEAT + tid];

    // X fragments: kst 0..5 full k16, kst6 k8 (f 96..103)
    uint32_t xhi[6][4], xlo[6][4], xh6[2], xl6[2];
    {
        const float* xr0 = x + ((size_t)(b0 + r0) * N_INST + i) * N_FEAT;
        const float* xr1 = x + ((size_t)(b0 + r1) * N_INST + i) * N_FEAT;
#pragma unroll
        for (int kst = 0; kst < 6; kst++) {
#pragma unroll
            for (int half = 0; half < 2; half++) {
                const int kk = kst * 16 + q * 2 + half * 8;   // <= 94, always in-bounds
                const float2 v0 = *reinterpret_cast<const float2*>(xr0 + kk);
                const float2 v1 = *reinterpret_cast<const float2*>(xr1 + kk);
                split_pair(v0.x, v0.y, xhi[kst][half * 2],     xlo[kst][half * 2]);
                split_pair(v1.x, v1.y, xhi[kst][half * 2 + 1], xlo[kst][half * 2 + 1]);
            }
        }
        const int kk = 96 + q * 2;
        float2 v0 = make_float2(0.f, 0.f), v1 = make_float2(0.f, 0.f);
        if (kk < N_FEAT) {
            v0 = *reinterpret_cast<const float2*>(xr0 + kk);
            v1 = *reinterpret_cast<const float2*>(xr1 + kk);
        }
        split_pair(v0.x, v0.y, xh6[0], xl6[0]);
        split_pair(v1.x, v1.y, xh6[1], xl6[1]);
    }
    __syncthreads();   // mask/bias visible

    // ======================= Phase A: 10 pair-iterations per group =======================
    float hacc[5][4];
#pragma unroll
    for (int nt = 0; nt < 5; nt++)
#pragma unroll
        for (int j = 0; j < 4; j++) hacc[nt][j] = 0.f;

    for (int cp = 0; cp < 10; cp++) {
        BARG(barid);                        // other slot's consumers done
        if (cp + 1 < 10) {
            stageG(rb + ((cp + 1) & 1) * RING_STRIDE,
                   imgAg + (size_t)(cp + 1) * SLOTA, SLOTA, tg);
            CP_COMMIT();
        }
        cp_waitn(cp + 1 < 10 ? 1 : 0);
        BARG(barid);                        // slot cp&1 visible to group

        const char* base = rbp + (cp & 1) * RING_STRIDE;
#pragma unroll
        for (int cc = 0; cc < 2; cc++) {
            const int c = 2 * (g * 10 + cp) + cc;
            const char* buf = base + cc * IMGA_C;
            float d[5][4];
#pragma unroll
            for (int nt = 0; nt < 5; nt++)
#pragma unroll
                for (int j = 0; j < 4; j++) d[nt][j] = 0.f;

#pragma unroll
            for (int kst = 0; kst < 6; kst++) {
                uint4 wv[5];
#pragma unroll
                for (int nt = 0; nt < 5; nt++)
                    wv[nt] = *reinterpret_cast<const uint4*>(buf + (((kst * 5 + nt) * 32 + T) << 4));
#pragma unroll
                for (int nt = 0; nt < 5; nt++) mma_bf16(d[nt], xhi[kst], wv[nt].x, wv[nt].y);
#pragma unroll
                for (int nt = 0; nt < 5; nt++) mma_bf16(d[nt], xhi[kst], wv[nt].z, wv[nt].w);
#pragma unroll
                for (int nt = 0; nt < 5; nt++) mma_bf16(d[nt], xlo[kst], wv[nt].x, wv[nt].y);
            }
            {   // kst 6: k8 (f 96..103)
                uint4 wv[5];
#pragma unroll
                for (int nt = 0; nt < 5; nt++)
                    wv[nt] = *reinterpret_cast<const uint4*>(buf + (((6 * 5 + nt) * 32 + T) << 4));
#pragma unroll
                for (int nt = 0; nt < 5; nt++) mma_bf16_k8(d[nt], xh6[0], xh6[1], wv[nt].x);
#pragma unroll
                for (int nt = 0; nt < 5; nt++) mma_bf16_k8(d[nt], xh6[0], xh6[1], wv[nt].z);
#pragma unroll
                for (int nt = 0; nt < 5; nt++) mma_bf16_k8(d[nt], xl6[0], xl6[1], wv[nt].x);
            }
            const float m0 = mskS[c * 128 + r0];
            const float m1 = mskS[c * 128 + r1];
#pragma unroll
            for (int nt = 0; nt < 5; nt++) {
                hacc[nt][0] = fmaf(m0, d[nt][0], hacc[nt][0]);
                hacc[nt][1] = fmaf(m0, d[nt][1], hacc[nt][1]);
                hacc[nt][2] = fmaf(m1, d[nt][2], hacc[nt][2]);
                hacc[nt][3] = fmaf(m1, d[nt][3], hacc[nt][3]);
            }
        }
    }

    // write group partial h
    {
        float* hp = g ? hp1 : hp0;
#pragma unroll
        for (int nt = 0; nt < 5; nt++) {
            const int col = nt * 8 + q * 2;
            *reinterpret_cast<float2*>(&hp[r0 * N_HID + col]) = make_float2(hacc[nt][0], hacc[nt][1]);
            *reinterpret_cast<float2*>(&hp[r1 * N_HID + col]) = make_float2(hacc[nt][2], hacc[nt][3]);
        }
    }
    // stage this group's B pair 0 into slot 0 (its A data long consumed)
    stageG(rb, imgBg, SLOTB, tg); CP_COMMIT();
    __syncthreads();   // both partials visible

    // h fragments from summed partials: kst 0,1 k16; kst2 k8 (h 32..39)
    uint32_t hh[2][4], hl[2][4], hh2[2], hl2[2];
#pragma unroll
    for (int kst = 0; kst < 2; kst++) {
#pragma unroll
        for (int half = 0; half < 2; half++) {
            const int kk = kst * 16 + q * 2 + half * 8;
            const float2 a0 = *reinterpret_cast<const float2*>(&hp0[r0 * N_HID + kk]);
            const float2 b0v = *reinterpret_cast<const float2*>(&hp1[r0 * N_HID + kk]);
            const float2 a1 = *reinterpret_cast<const float2*>(&hp0[r1 * N_HID + kk]);
            const float2 b1v = *reinterpret_cast<const float2*>(&hp1[r1 * N_HID + kk]);
            split_pair(a0.x + b0v.x, a0.y + b0v.y, hh[kst][half * 2],     hl[kst][half * 2]);
            split_pair(a1.x + b1v.x, a1.y + b1v.y, hh[kst][half * 2 + 1], hl[kst][half * 2 + 1]);
        }
    }
    {
        const int kk = 32 + q * 2;
        const float2 a0 = *reinterpret_cast<const float2*>(&hp0[r0 * N_HID + kk]);
        const float2 b0v = *reinterpret_cast<const float2*>(&hp1[r0 * N_HID + kk]);
        const float2 a1 = *reinterpret_cast<const float2*>(&hp0[r1 * N_HID + kk]);
        const float2 b1v = *reinterpret_cast<const float2*>(&hp1[r1 * N_HID + kk]);
        split_pair(a0.x + b0v.x, a0.y + b0v.y, hh2[0], hl2[0]);
        split_pair(a1.x + b1v.x, a1.y + b1v.y, hh2[1], hl2[1]);
    }

    // ======================= Phase B: 10 pair-iterations per group =======================
    float oacc[13][4];
#pragma unroll
    for (int nt = 0; nt < 13; nt++)
#pragma unroll
        for (int j = 0; j < 4; j++) oacc[nt][j] = 0.f;

    for (int cp = 0; cp < 10; cp++) {
        BARG(barid);
        if (cp + 1 < 10) {
            stageG(rb + ((cp + 1) & 1) * RING_STRIDE,
                   imgBg + (size_t)(cp + 1) * SLOTB, SLOTB, tg);
            CP_COMMIT();
        }
        cp_waitn(cp + 1 < 10 ? 1 : 0);
        BARG(barid);

        const char* base = rbp + (cp & 1) * RING_STRIDE;
#pragma unroll
        for (int cc = 0; cc < 2; cc++) {
            const int c = 2 * (g * 10 + cp) + cc;
            const char* buf = base + cc * IMGB_C;
            const uint32_t keep0 = (mskS[c * 128 + r0] != 0.f) ? 0xFFFFFFFFu : 0u;
            const uint32_t keep1 = (mskS[c * 128 + r1] != 0.f) ? 0xFFFFFFFFu : 0u;

#pragma unroll
            for (int kst = 0; kst < 2; kst++) {            // k16 steps
                uint32_t ah[4], al[4];
                ah[0] = hh[kst][0] & keep0; ah[1] = hh[kst][1] & keep1;
                ah[2] = hh[kst][2] & keep0; ah[3] = hh[kst][3] & keep1;
                al[0] = hl[kst][0] & keep0; al[1] = hl[kst][1] & keep1;
                al[2] = hl[kst][2] & keep0; al[3] = hl[kst][3] & keep1;
                {
                    uint4 wv[7];
#pragma unroll
                    for (int j = 0; j < 7; j++)
                        wv[j] = *reinterpret_cast<const uint4*>(buf + (((kst * 13 + j) * 32 + T) << 4));
#pragma unroll
                    for (int j = 0; j < 7; j++) mma_bf16(oacc[j], ah, wv[j].x, wv[j].y);
#pragma unroll
                    for (int j = 0; j < 7; j++) mma_bf16(oacc[j], ah, wv[j].z, wv[j].w);
#pragma unroll
                    for (int j = 0; j < 7; j++) mma_bf16(oacc[j], al, wv[j].x, wv[j].y);
                }
                {
                    uint4 wv[6];
#pragma unroll
                    for (int j = 0; j < 6; j++)
                        wv[j] = *reinterpret_cast<const uint4*>(buf + (((kst * 13 + 7 + j) * 32 + T) << 4));
#pragma unroll
                    for (int j = 0; j < 6; j++) mma_bf16(oacc[7 + j], ah, wv[j].x, wv[j].y);
#pragma unroll
                    for (int j = 0; j < 6; j++) mma_bf16(oacc[7 + j], ah, wv[j].z, wv[j].w);
#pragma unroll
                    for (int j = 0; j < 6; j++) mma_bf16(oacc[7 + j], al, wv[j].x, wv[j].y);
                }
            }
            {   // kst 2: k8 (h 32..39)
                const uint32_t a0 = hh2[0] & keep0, a1 = hh2[1] & keep1;
                const uint32_t c0 = hl2[0] & keep0, c1 = hl2[1] & keep1;
                {
                    uint4 wv[7];
#pragma unroll
                    for (int j = 0; j < 7; j++)
                        wv[j] = *reinterpret_cast<const uint4*>(buf + (((2 * 13 + j) * 32 + T) << 4));
#pragma unroll
                    for (int j = 0; j < 7; j++) mma_bf16_k8(oacc[j], a0, a1, wv[j].x);
#pragma unroll
                    for (int j = 0; j < 7; j++) mma_bf16_k8(oacc[j], a0, a1, wv[j].z);
#pragma unroll
                    for (int j = 0; j < 7; j++) mma_bf16_k8(oacc[j], c0, c1, wv[j].x);
                }
                {
                    uint4 wv[6];
#pragma unroll
                    for (int j = 0; j < 6; j++)
                        wv[j] = *reinterpret_cast<const uint4*>(buf + (((2 * 13 + 7 + j) * 32 + T) << 4));
#pragma unroll
                    for (int j = 0; j < 6; j++) mma_bf16_k8(oacc[7 + j], a0, a1, wv[j].x);
#pragma unroll
                    for (int j = 0; j < 6; j++) mma_bf16_k8(oacc[7 + j], a0, a1, wv[j].z);
#pragma unroll
                    for (int j = 0; j < 6; j++) mma_bf16_k8(oacc[7 + j], c0, c1, wv[j].x);
                }
            }
        }
    }

    // ======================= cross-group reduce + epilogue =======================
    float* stash = reinterpret_cast<float*>(smem);   // [128][104], ring dead
    __syncthreads();
    if (g == 1) {
#pragma unroll
        for (int nt = 0; nt < 13; nt++) {
            const int col = nt * 8 + q * 2;
            *reinterpret_cast<float2*>(&stash[r0 * 104 + col]) = make_float2(oacc[nt][0], oacc[nt][1]);
            *reinterpret_cast<float2*>(&stash[r1 * 104 + col]) = make_float2(oacc[nt][2], oacc[nt][3]);
        }
    }
    __syncthreads();
    if (g == 0) {
        float* o0 = out + ((size_t)(b0 + r0) * N_INST + i) * N_FEAT;
        float* o1 = out + ((size_t)(b0 + r1) * N_INST + i) * N_FEAT;
#pragma unroll
        for (int nt = 0; nt < 13; nt++) {
            const int col = nt * 8 + q * 2;
            if (col < N_FEAT) {
                const float2 s0 = *reinterpret_cast<const float2*>(&stash[r0 * 104 + col]);
                const float2 s1 = *reinterpret_cast<const float2*>(&stash[r1 * 104 + col]);
                const float2 bf = *reinterpret_cast<const float2*>(&biasS[col]);
                float2 a, b;
                a.x = fmaxf(oacc[nt][0] + s0.x + bf.x, 0.f);
                a.y = fmaxf(oacc[nt][1] + s0.y + bf.y, 0.f);
                b.x = fmaxf(oacc[nt][2] + s1.x + bf.x, 0.f);
                b.y = fmaxf(oacc[nt][3] + s1.y + bf.y, 0.f);
                *reinterpret_cast<float2*>(o0 + col) = a;
                *reinterpret_cast<float2*>(o1 + col) = b;
            }
        }
    }
}

// ---------------------------------------------------------------------------
extern "C" void kernel_launch(void* const* d_in, const int* in_sizes, int n_in,
                              void* d_out, int out_size) {
    (void)in_sizes; (void)n_in; (void)out_size;
    const float* x    = (const float*)d_in[0];
    const float* mask = (const float*)d_in[1];
    const float* A    = (const float*)d_in[2];
    const float* Bp   = (const float*)d_in[3];
    const float* bfin = (const float*)d_in[4];
    float* out = (float*)d_out;

    cudaFuncSetAttribute(tmsspd_main_kernel,
                         cudaFuncAttributeMaxDynamicSharedMemorySize, SM_TOTAL);

    compute_G_kernel<<<N_INST * NC, 256>>>(A, Bp);

    dim3 grid(B_SZ / 128, N_INST);
    tmsspd_main_kernel<<<grid, NTHR, SM_TOTAL>>>(x, mask, bfin, out);
}